// round 1
// baseline (speedup 1.0000x reference)
#include <cuda_runtime.h>
#include <math.h>

// ---------------- problem constants ----------------
constexpr int Dd   = 512;
constexpr int Hn   = 8;
constexpr int DFFd = 2048;
constexpr int KWn  = 31;
constexpr int Ln   = 2;
constexpr int Bn   = 4;
constexpr int Tn   = 1024;
constexpr int DKn  = 64;
constexpr int Pn   = 2 * Tn - 1;      // 2047
constexpr int BTn  = Bn * Tn;         // 4096
constexpr float EPSf   = 1e-5f;
constexpr float SCALEf = 0.125f;      // 1/sqrt(64)

// ---------------- device scratch (allocation-free) ----------------
__device__ float g_X  [BTn * Dd];
__device__ float g_H  [BTn * Dd];
__device__ float g_FF [BTn * DFFd];
__device__ float g_Q  [BTn * Dd];
__device__ float g_K  [BTn * Dd];
__device__ float g_V  [BTn * Dd];
__device__ float g_P  [Pn * Dd];
__device__ float g_S  [(size_t)Bn * Hn * Tn * Tn];  // 128 MB scores
__device__ float g_CTX[BTn * Dd];
__device__ float g_Y2 [BTn * 2 * Dd];
__device__ float g_CV [Bn * Dd * Tn];
__device__ float g_CV2[Bn * Dd * Tn];
__device__ float g_mu [Dd];
__device__ float g_rstd[Dd];

__device__ __forceinline__ float sigf(float x) { return 1.0f / (1.0f + expf(-x)); }

// ---------------- generic batched tiled GEMM ----------------
// C[z] = epilogue(A[z] (MxK, lda) @ W[z] (KxN, ldw) + bias)
// MODE: 0 = bias only, 1 = silu(.+bias), 2 = res + (.), 3 = res + 0.5*(.)
template <int MODE>
__global__ void __launch_bounds__(256) gemm64(
    const float* __restrict__ A, int lda, long long sA,
    const float* __restrict__ W, int ldw, long long sW,
    const float* __restrict__ bias,
    const float* __restrict__ res, long long sR,
    float* __restrict__ C, int ldc, long long sC,
    int M, int N, int Kd)
{
    __shared__ __align__(16) float As[16][64];
    __shared__ __align__(16) float Bs[16][64];
    const int z = blockIdx.z;
    A += (size_t)z * sA;
    W += (size_t)z * sW;
    C += (size_t)z * sC;
    if (res) res += (size_t)z * sR;

    const int bm = blockIdx.y * 64, bn = blockIdx.x * 64;
    const int tid = threadIdx.x;
    const int tx = tid & 15, ty = tid >> 4;
    const int arow = tid >> 2, acol = (tid & 3) << 2;   // A tile loader
    const int wrow = tid >> 4, wcol = (tid & 15) << 2;  // W tile loader

    float acc[4][4] = {};

    for (int k0 = 0; k0 < Kd; k0 += 16) {
        float4 av = make_float4(0.f, 0.f, 0.f, 0.f);
        if (bm + arow < M)
            av = *(const float4*)&A[(size_t)(bm + arow) * lda + k0 + acol];
        As[acol + 0][arow] = av.x;
        As[acol + 1][arow] = av.y;
        As[acol + 2][arow] = av.z;
        As[acol + 3][arow] = av.w;
        float4 wv = *(const float4*)&W[(size_t)(k0 + wrow) * ldw + bn + wcol];
        *(float4*)&Bs[wrow][wcol] = wv;
        __syncthreads();
#pragma unroll
        for (int k = 0; k < 16; k++) {
            float4 a4 = *(const float4*)&As[k][ty * 4];
            float4 b4 = *(const float4*)&Bs[k][tx * 4];
            float a[4] = {a4.x, a4.y, a4.z, a4.w};
            float b[4] = {b4.x, b4.y, b4.z, b4.w};
#pragma unroll
            for (int i = 0; i < 4; i++)
#pragma unroll
                for (int j = 0; j < 4; j++)
                    acc[i][j] += a[i] * b[j];
        }
        __syncthreads();
    }

#pragma unroll
    for (int i = 0; i < 4; i++) {
        int row = bm + ty * 4 + i;
        if (row >= M) break;
#pragma unroll
        for (int j = 0; j < 4; j++) {
            int col = bn + tx * 4 + j;
            float v = acc[i][j];
            if (bias) v += bias[col];
            if (MODE == 1) v = v * sigf(v);
            if (MODE == 2) v = res[(size_t)row * ldc + col] + v;
            if (MODE == 3) v = res[(size_t)row * ldc + col] + 0.5f * v;
            C[(size_t)row * ldc + col] = v;
        }
    }
}

// ---------------- LayerNorm: one block per row, D=512, 256 threads ----------------
__global__ void __launch_bounds__(256) ln_kernel(
    const float* __restrict__ x, const float* __restrict__ s,
    const float* __restrict__ b, float* __restrict__ out)
{
    __shared__ float red[256];
    const int row = blockIdx.x;
    const float* xr = x + (size_t)row * Dd;
    const int tid = threadIdx.x;
    float v0 = xr[tid], v1 = xr[tid + 256];
    red[tid] = v0 + v1;
    __syncthreads();
    for (int o = 128; o > 0; o >>= 1) {
        if (tid < o) red[tid] += red[tid + o];
        __syncthreads();
    }
    float mean = red[0] * (1.0f / Dd);
    __syncthreads();
    float d0 = v0 - mean, d1 = v1 - mean;
    red[tid] = d0 * d0 + d1 * d1;
    __syncthreads();
    for (int o = 128; o > 0; o >>= 1) {
        if (tid < o) red[tid] += red[tid + o];
        __syncthreads();
    }
    float rstd = rsqrtf(red[0] * (1.0f / Dd) + EPSf);
    out[(size_t)row * Dd + tid]       = d0 * rstd * s[tid]       + b[tid];
    out[(size_t)row * Dd + tid + 256] = d1 * rstd * s[tid + 256] + b[tid + 256];
}

// ---------------- rel-pos attention scores ----------------
// S[b,h,t,s] = ((q+u)·k[s] + (q+v)·p[T-1-t+s]) * SCALE   (rel_shift folded into index)
__global__ void __launch_bounds__(256) attn_scores(
    const float* __restrict__ Q, const float* __restrict__ Km,
    const float* __restrict__ Pm,
    const float* __restrict__ bu, const float* __restrict__ bvv,
    float* __restrict__ S)
{
    __shared__ __align__(16) float qu[32 * 64];
    __shared__ __align__(16) float qv[32 * 64];
    __shared__ __align__(16) float kt[32 * 64];
    __shared__ __align__(16) float pw[63 * 64];
    const int z = blockIdx.z;
    const int b = z >> 3, h = z & 7;
    const int t0 = blockIdx.y << 5, s0 = blockIdx.x << 5;
    const int tid = threadIdx.x;
    const float* bup = bu + h * 64;
    const float* bvp = bvv + h * 64;
    for (int i = tid; i < 32 * 64; i += 256) {
        int r = i >> 6, d = i & 63;
        float q = Q[(size_t)(b * Tn + t0 + r) * Dd + h * 64 + d];
        qu[i] = q + bup[d];
        qv[i] = q + bvp[d];
        kt[i] = Km[(size_t)(b * Tn + s0 + r) * Dd + h * 64 + d];
    }
    const int base = (Tn - 32) - t0 + s0;   // = (T-1) - (t0+31) + s0, always in [0, P-63]
    for (int i = tid; i < 63 * 64; i += 256) {
        int r = i >> 6, d = i & 63;
        pw[i] = Pm[(size_t)(base + r) * Dd + h * 64 + d];
    }
    __syncthreads();

    const int tx = tid & 15, ty = tid >> 4;
    const int tl = ty * 2, sl = tx * 2;
    const float4* qu4 = (const float4*)qu;
    const float4* qv4 = (const float4*)qv;
    const float4* kt4 = (const float4*)kt;
    const float4* pw4 = (const float4*)pw;
    const int pr = 31 - tl + sl;  // local p-row for (tl,sl); (tl,sl+1)->pr+1, (tl+1,sl)->pr-1, (tl+1,sl+1)->pr
    float a00 = 0.f, a01 = 0.f, a10 = 0.f, a11 = 0.f;
#pragma unroll
    for (int d4 = 0; d4 < 16; d4++) {
        float4 u0 = qu4[tl * 16 + d4];
        float4 u1 = qu4[(tl + 1) * 16 + d4];
        float4 v0 = qv4[tl * 16 + d4];
        float4 v1 = qv4[(tl + 1) * 16 + d4];
        float4 k0 = kt4[sl * 16 + d4];
        float4 k1 = kt4[(sl + 1) * 16 + d4];
        float4 pz = pw4[pr * 16 + d4];
        float4 pp = pw4[(pr + 1) * 16 + d4];
        float4 pm = pw4[(pr - 1) * 16 + d4];
        a00 += u0.x*k0.x + u0.y*k0.y + u0.z*k0.z + u0.w*k0.w
             + v0.x*pz.x + v0.y*pz.y + v0.z*pz.z + v0.w*pz.w;
        a01 += u0.x*k1.x + u0.y*k1.y + u0.z*k1.z + u0.w*k1.w
             + v0.x*pp.x + v0.y*pp.y + v0.z*pp.z + v0.w*pp.w;
        a10 += u1.x*k0.x + u1.y*k0.y + u1.z*k0.z + u1.w*k0.w
             + v1.x*pm.x + v1.y*pm.y + v1.z*pm.z + v1.w*pm.w;
        a11 += u1.x*k1.x + u1.y*k1.y + u1.z*k1.z + u1.w*k1.w
             + v1.x*pz.x + v1.y*pz.y + v1.z*pz.z + v1.w*pz.w;
    }
    float* Sp = S + ((size_t)z * Tn + (t0 + tl)) * Tn + (s0 + sl);
    Sp[0]      = a00 * SCALEf;
    Sp[1]      = a01 * SCALEf;
    Sp[Tn]     = a10 * SCALEf;
    Sp[Tn + 1] = a11 * SCALEf;
}

// ---------------- row softmax over T=1024 ----------------
__global__ void __launch_bounds__(256) softmax_kernel(float* __restrict__ S)
{
    __shared__ float red[256];
    float4* p = (float4*)(S + (size_t)blockIdx.x * Tn);
    const int tid = threadIdx.x;
    float4 x = p[tid];
    float m = fmaxf(fmaxf(x.x, x.y), fmaxf(x.z, x.w));
    red[tid] = m;
    __syncthreads();
    for (int o = 128; o > 0; o >>= 1) {
        if (tid < o) red[tid] = fmaxf(red[tid], red[tid + o]);
        __syncthreads();
    }
    m = red[0];
    __syncthreads();
    x.x = expf(x.x - m); x.y = expf(x.y - m); x.z = expf(x.z - m); x.w = expf(x.w - m);
    red[tid] = x.x + x.y + x.z + x.w;
    __syncthreads();
    for (int o = 128; o > 0; o >>= 1) {
        if (tid < o) red[tid] += red[tid + o];
        __syncthreads();
    }
    float inv = 1.0f / red[0];
    x.x *= inv; x.y *= inv; x.z *= inv; x.w *= inv;
    p[tid] = x;
}

// ---------------- GLU + transpose (B,T,2D) -> (B,D,T) ----------------
__global__ void __launch_bounds__(256) glu_kernel(const float* __restrict__ Y2,
                                                  float* __restrict__ CV)
{
    int idx = blockIdx.x * 256 + threadIdx.x;      // over B*D*T
    int t = idx & (Tn - 1);
    int bd = idx >> 10;
    int d = bd & (Dd - 1);
    int b = bd >> 9;
    size_t ybase = (size_t)(b * Tn + t) * (2 * Dd);
    float a = Y2[ybase + d];
    float g = Y2[ybase + Dd + d];
    CV[idx] = a * sigf(g);
}

// ---------------- depthwise conv K=31, pad 15 ----------------
__global__ void __launch_bounds__(128) dwconv_kernel(
    const float* __restrict__ CV, const float* __restrict__ w,
    const float* __restrict__ bias, float* __restrict__ out)
{
    __shared__ float sin_[128 + 30];
    __shared__ float sw[31];
    const int t0 = blockIdx.x * 128;
    const int d = blockIdx.y;
    const int b = blockIdx.z;
    const float* ip = CV + ((size_t)b * Dd + d) * Tn;
    const int tid = threadIdx.x;
    for (int i = tid; i < 158; i += 128) {
        int t = t0 - 15 + i;
        sin_[i] = (t >= 0 && t < Tn) ? ip[t] : 0.0f;
    }
    if (tid < 31) sw[tid] = w[d * KWn + tid];
    __syncthreads();
    float acc = bias[d];
#pragma unroll
    for (int k = 0; k < 31; k++) acc += sin_[tid + k] * sw[k];
    out[((size_t)b * Dd + d) * Tn + t0 + tid] = acc;
}

// ---------------- BatchNorm stats (mean/var over B*T per channel) ----------------
__global__ void __launch_bounds__(256) bn_stats(const float* __restrict__ y)
{
    __shared__ float rs[256], rs2[256];
    const int d = blockIdx.x;
    const int tid = threadIdx.x;
    float s = 0.f, s2 = 0.f;
    for (int b = 0; b < Bn; b++) {
        const float* p = y + ((size_t)b * Dd + d) * Tn;
        for (int t = tid; t < Tn; t += 256) {
            float v = p[t];
            s += v;
            s2 += v * v;
        }
    }
    rs[tid] = s; rs2[tid] = s2;
    __syncthreads();
    for (int o = 128; o > 0; o >>= 1) {
        if (tid < o) { rs[tid] += rs[tid + o]; rs2[tid] += rs2[tid + o]; }
        __syncthreads();
    }
    if (tid == 0) {
        float mu = rs[0] * (1.0f / (Bn * Tn));
        float var = rs2[0] * (1.0f / (Bn * Tn)) - mu * mu;
        g_mu[d] = mu;
        g_rstd[d] = rsqrtf(var + EPSf);
    }
}

// ---------------- BN apply + SiLU + transpose (B,D,T) -> (B,T,D) ----------------
__global__ void __launch_bounds__(256) bn_apply(
    const float* __restrict__ y, const float* __restrict__ g,
    const float* __restrict__ bt, float* __restrict__ out)
{
    const int d = blockIdx.x;
    const int b = blockIdx.y;
    const int tid = threadIdx.x;
    float mu = g_mu[d], r = g_rstd[d], gg = g[d], bb = bt[d];
    const float* p = y + ((size_t)b * Dd + d) * Tn;
    for (int t = tid; t < Tn; t += 256) {
        float v = (p[t] - mu) * r * gg + bb;
        v = v * sigf(v);
        out[(size_t)(b * Tn + t) * Dd + d] = v;
    }
}

// ---------------- copy ----------------
__global__ void __launch_bounds__(256) copy_kernel(const float* __restrict__ in,
                                                   float* __restrict__ out, int n)
{
    int i = blockIdx.x * 256 + threadIdx.x;
    if (i < n) out[i] = in[i];
}

// ---------------- host-side launch helpers ----------------
static void launch_gemm(int mode,
                        const float* A, int lda, long long sA,
                        const float* W, int ldw, long long sW,
                        const float* bias,
                        const float* res, long long sR,
                        float* C, int ldc, long long sC,
                        int M, int N, int Kd, int batch)
{
    dim3 g(N / 64, (M + 63) / 64, batch);
    switch (mode) {
        case 0: gemm64<0><<<g, 256>>>(A, lda, sA, W, ldw, sW, bias, res, sR, C, ldc, sC, M, N, Kd); break;
        case 1: gemm64<1><<<g, 256>>>(A, lda, sA, W, ldw, sW, bias, res, sR, C, ldc, sC, M, N, Kd); break;
        case 2: gemm64<2><<<g, 256>>>(A, lda, sA, W, ldw, sW, bias, res, sR, C, ldc, sC, M, N, Kd); break;
        case 3: gemm64<3><<<g, 256>>>(A, lda, sA, W, ldw, sW, bias, res, sR, C, ldc, sC, M, N, Kd); break;
    }
}

extern "C" void kernel_launch(void* const* d_in, const int* in_sizes, int n_in,
                              void* d_out, int out_size)
{
    const float* in_x   = (const float*)d_in[0];
    const float* pos    = (const float*)d_in[1];
    const float* ln_s   = (const float*)d_in[2];
    const float* ln_b   = (const float*)d_in[3];
    const float* ff1_w1 = (const float*)d_in[4];
    const float* ff1_b1 = (const float*)d_in[5];
    const float* ff1_w2 = (const float*)d_in[6];
    const float* ff1_b2 = (const float*)d_in[7];
    const float* ff2_w1 = (const float*)d_in[8];
    const float* ff2_b1 = (const float*)d_in[9];
    const float* ff2_w2 = (const float*)d_in[10];
    const float* ff2_b2 = (const float*)d_in[11];
    const float* wq     = (const float*)d_in[12];
    const float* bq     = (const float*)d_in[13];
    const float* wk     = (const float*)d_in[14];
    const float* bk     = (const float*)d_in[15];
    const float* wv     = (const float*)d_in[16];
    const float* bv     = (const float*)d_in[17];
    const float* wp     = (const float*)d_in[18];
    const float* wo     = (const float*)d_in[19];
    const float* bo     = (const float*)d_in[20];
    const float* bias_u = (const float*)d_in[21];
    const float* bias_v = (const float*)d_in[22];
    const float* pw1_w  = (const float*)d_in[23];
    const float* pw1_b  = (const float*)d_in[24];
    const float* dw_w   = (const float*)d_in[25];
    const float* dw_b   = (const float*)d_in[26];
    const float* bn_g   = (const float*)d_in[27];
    const float* bn_b   = (const float*)d_in[28];
    const float* pw2_w  = (const float*)d_in[29];
    const float* pw2_b  = (const float*)d_in[30];
    (void)in_sizes; (void)n_in; (void)out_size;

    float *X, *Hb, *FF, *Qb, *Kb, *Vb, *Pb, *Sb, *CTX, *Y2, *CV, *CV2;
    cudaGetSymbolAddress((void**)&X,   g_X);
    cudaGetSymbolAddress((void**)&Hb,  g_H);
    cudaGetSymbolAddress((void**)&FF,  g_FF);
    cudaGetSymbolAddress((void**)&Qb,  g_Q);
    cudaGetSymbolAddress((void**)&Kb,  g_K);
    cudaGetSymbolAddress((void**)&Vb,  g_V);
    cudaGetSymbolAddress((void**)&Pb,  g_P);
    cudaGetSymbolAddress((void**)&Sb,  g_S);
    cudaGetSymbolAddress((void**)&CTX, g_CTX);
    cudaGetSymbolAddress((void**)&Y2,  g_Y2);
    cudaGetSymbolAddress((void**)&CV,  g_CV);
    cudaGetSymbolAddress((void**)&CV2, g_CV2);

    copy_kernel<<<(BTn * Dd) / 256, 256>>>(in_x, X, BTn * Dd);

    for (int l = 0; l < Ln; ++l) {
        const float* lnS = ln_s + (size_t)l * 5 * Dd;
        const float* lnB = ln_b + (size_t)l * 5 * Dd;

        // ---- macaron FFN 1 (half residual) ----
        ln_kernel<<<BTn, 256>>>(X, lnS, lnB, Hb);
        launch_gemm(1, Hb, Dd, 0, ff1_w1 + (size_t)l * Dd * DFFd, DFFd, 0,
                    ff1_b1 + (size_t)l * DFFd, nullptr, 0, FF, DFFd, 0, BTn, DFFd, Dd, 1);
        launch_gemm(3, FF, DFFd, 0, ff1_w2 + (size_t)l * DFFd * Dd, Dd, 0,
                    ff1_b2 + (size_t)l * Dd, X, 0, X, Dd, 0, BTn, Dd, DFFd, 1);

        // ---- rel-pos MHSA ----
        ln_kernel<<<BTn, 256>>>(X, lnS + Dd, lnB + Dd, Hb);
        launch_gemm(0, Hb, Dd, 0, wq + (size_t)l * Dd * Dd, Dd, 0,
                    bq + (size_t)l * Dd, nullptr, 0, Qb, Dd, 0, BTn, Dd, Dd, 1);
        launch_gemm(0, Hb, Dd, 0, wk + (size_t)l * Dd * Dd, Dd, 0,
                    bk + (size_t)l * Dd, nullptr, 0, Kb, Dd, 0, BTn, Dd, Dd, 1);
        launch_gemm(0, Hb, Dd, 0, wv + (size_t)l * Dd * Dd, Dd, 0,
                    bv + (size_t)l * Dd, nullptr, 0, Vb, Dd, 0, BTn, Dd, Dd, 1);
        launch_gemm(0, pos, Dd, 0, wp + (size_t)l * Dd * Dd, Dd, 0,
                    nullptr, nullptr, 0, Pb, Dd, 0, Pn, Dd, Dd, 1);

        attn_scores<<<dim3(Tn / 32, Tn / 32, Bn * Hn), 256>>>(
            Qb, Kb, Pb, bias_u + (size_t)l * Hn * DKn, bias_v + (size_t)l * Hn * DKn, Sb);
        softmax_kernel<<<Bn * Hn * Tn, 256>>>(Sb);

        for (int h = 0; h < Hn; ++h) {
            launch_gemm(0,
                        Sb + (size_t)h * Tn * Tn, Tn, (long long)Hn * Tn * Tn,
                        Vb + h * DKn, Dd, (long long)Tn * Dd,
                        nullptr, nullptr, 0,
                        CTX + h * DKn, Dd, (long long)Tn * Dd,
                        Tn, DKn, Tn, Bn);
        }
        launch_gemm(2, CTX, Dd, 0, wo + (size_t)l * Dd * Dd, Dd, 0,
                    bo + (size_t)l * Dd, X, 0, X, Dd, 0, BTn, Dd, Dd, 1);

        // ---- conv module ----
        ln_kernel<<<BTn, 256>>>(X, lnS + 2 * Dd, lnB + 2 * Dd, Hb);
        launch_gemm(0, Hb, Dd, 0, pw1_w + (size_t)l * Dd * 2 * Dd, 2 * Dd, 0,
                    pw1_b + (size_t)l * 2 * Dd, nullptr, 0, Y2, 2 * Dd, 0, BTn, 2 * Dd, Dd, 1);
        glu_kernel<<<(Bn * Dd * Tn) / 256, 256>>>(Y2, CV);
        dwconv_kernel<<<dim3(Tn / 128, Dd, Bn), 128>>>(
            CV, dw_w + (size_t)l * Dd * KWn, dw_b + (size_t)l * Dd, CV2);
        bn_stats<<<Dd, 256>>>(CV2);
        bn_apply<<<dim3(Dd, Bn), 256>>>(CV2, bn_g + (size_t)l * Dd, bn_b + (size_t)l * Dd, Hb);
        launch_gemm(2, Hb, Dd, 0, pw2_w + (size_t)l * Dd * Dd, Dd, 0,
                    pw2_b + (size_t)l * Dd, X, 0, X, Dd, 0, BTn, Dd, Dd, 1);

        // ---- macaron FFN 2 (half residual) ----
        ln_kernel<<<BTn, 256>>>(X, lnS + 3 * Dd, lnB + 3 * Dd, Hb);
        launch_gemm(1, Hb, Dd, 0, ff2_w1 + (size_t)l * Dd * DFFd, DFFd, 0,
                    ff2_b1 + (size_t)l * DFFd, nullptr, 0, FF, DFFd, 0, BTn, DFFd, Dd, 1);
        launch_gemm(3, FF, DFFd, 0, ff2_w2 + (size_t)l * DFFd * Dd, Dd, 0,
                    ff2_b2 + (size_t)l * Dd, X, 0, X, Dd, 0, BTn, Dd, DFFd, 1);

        // ---- final per-layer LN ----
        float* outp = (l == Ln - 1) ? (float*)d_out : X;
        ln_kernel<<<BTn, 256>>>(X, lnS + 4 * Dd, lnB + 4 * Dd, outp);
    }
}

// round 2
// speedup vs baseline: 1.4695x; 1.4695x over previous
#include <cuda_runtime.h>
#include <math.h>

// ---------------- problem constants ----------------
constexpr int Dd   = 512;
constexpr int Hn   = 8;
constexpr int DFFd = 2048;
constexpr int KWn  = 31;
constexpr int Ln   = 2;
constexpr int Bn   = 4;
constexpr int Tn   = 1024;
constexpr int DKn  = 64;
constexpr int Pn   = 2 * Tn - 1;      // 2047
constexpr int BTn  = Bn * Tn;         // 4096
constexpr float EPSf   = 1e-5f;
constexpr float SCALEf = 0.125f;      // 1/sqrt(64)

// ---------------- device scratch (allocation-free) ----------------
__device__ float g_X  [BTn * Dd];
__device__ float g_H  [BTn * Dd];
__device__ float g_FF [BTn * DFFd];
__device__ float g_Q  [BTn * Dd];
__device__ float g_K  [BTn * Dd];
__device__ float g_V  [BTn * Dd];
__device__ float g_P  [Pn * Dd];
__device__ float g_S  [(size_t)Bn * Hn * Tn * Tn];  // 128 MB scores
__device__ float g_CTX[BTn * Dd];
__device__ float g_Y2 [BTn * 2 * Dd];
__device__ float g_CV [Bn * Dd * Tn];
__device__ float g_CV2[Bn * Dd * Tn];
__device__ float g_mu [Dd];
__device__ float g_rstd[Dd];

__device__ __forceinline__ float sigf(float x) { return 1.0f / (1.0f + expf(-x)); }

__device__ __forceinline__ unsigned f2tf32(float x) {
    unsigned u;
    asm("cvt.rna.tf32.f32 %0, %1;" : "=r"(u) : "f"(x));
    return u;
}

// =======================================================================
// TF32 tensor-core GEMM: C = epilogue(A (MxK, lda) @ W (KxN, ldw) + bias)
// Tile: BM=128, BN=64, BK=32. 256 threads = 8 warps (4 x 2), each warp
// computes 32x32 via 2x4 mma.sync.m16n8k8 fragments.
// MODE: 0 = (+bias), 1 = silu(+bias), 2 = res + (.), 3 = res + 0.5*(.)
// AV: blockIdx.z decodes (b,h) for the attn-prob @ V batched GEMM.
// Requirements: N % 64 == 0, K % 32 == 0. M arbitrary (predicated).
// =======================================================================
template <int MODE, bool AV>
__global__ void __launch_bounds__(256) tf32gemm(
    const float* __restrict__ A, int lda,
    const float* __restrict__ W, int ldw,
    const float* __restrict__ bias,
    const float* __restrict__ res,
    float* __restrict__ C, int ldc,
    int M, int N, int Kd)
{
    // padded so fragment reads AND tile stores are bank-conflict-free
    __shared__ unsigned As[128][36];   // [m][k], bank = 4m + k
    __shared__ unsigned Bs[32][72];    // [k][n], bank = 8k + n

    if (AV) {
        int z = blockIdx.z;                       // z = b*8 + h
        A += (size_t)z * Tn * Tn;                 // S[b][h] (T x T)
        size_t off = (size_t)(z >> 3) * Tn * Dd + (size_t)(z & 7) * DKn;
        W += off;                                 // V[b][:, h*64 ...]
        C += off;                                 // CTX same layout
    }

    const int bm = blockIdx.y * 128, bn = blockIdx.x * 64;
    const int tid  = threadIdx.x;
    const int warp = tid >> 5, lane = tid & 31;
    const int g = lane >> 2, t = lane & 3;        // groupID, thread-in-group
    const int wm = (warp >> 1) * 32, wn = (warp & 1) * 32;

    float acc[2][4][4] = {};
    float4 pa[4];
    float4 pb[2];

    auto loadG = [&](int k0) {
#pragma unroll
        for (int i = 0; i < 4; i++) {
            int lin = i * 256 + tid;
            int row = lin >> 3, c4 = lin & 7;
            if (bm + row < M)
                pa[i] = *(const float4*)&A[(size_t)(bm + row) * lda + k0 + 4 * c4];
            else
                pa[i] = make_float4(0.f, 0.f, 0.f, 0.f);
        }
#pragma unroll
        for (int i = 0; i < 2; i++) {
            int lin = i * 256 + tid;
            int kr = lin >> 4, c4 = lin & 15;
            pb[i] = *(const float4*)&W[(size_t)(k0 + kr) * ldw + bn + 4 * c4];
        }
    };
    auto storeS = [&]() {
#pragma unroll
        for (int i = 0; i < 4; i++) {
            int lin = i * 256 + tid;
            int row = lin >> 3, c4 = lin & 7;
            unsigned* p = &As[row][4 * c4];
            p[0] = f2tf32(pa[i].x); p[1] = f2tf32(pa[i].y);
            p[2] = f2tf32(pa[i].z); p[3] = f2tf32(pa[i].w);
        }
#pragma unroll
        for (int i = 0; i < 2; i++) {
            int lin = i * 256 + tid;
            int kr = lin >> 4, c4 = lin & 15;
            unsigned* p = &Bs[kr][4 * c4];
            p[0] = f2tf32(pb[i].x); p[1] = f2tf32(pb[i].y);
            p[2] = f2tf32(pb[i].z); p[3] = f2tf32(pb[i].w);
        }
    };

    const int nk = Kd >> 5;
    loadG(0);
    storeS();
    __syncthreads();

    for (int kb = 0; kb < nk; kb++) {
        if (kb + 1 < nk) loadG((kb + 1) * 32);

#pragma unroll
        for (int kt = 0; kt < 4; kt++) {
            const int k = kt * 8 + t;
            unsigned a[2][4];
#pragma unroll
            for (int mt = 0; mt < 2; mt++) {
                int mb = wm + mt * 16 + g;
                a[mt][0] = As[mb][k];
                a[mt][1] = As[mb + 8][k];
                a[mt][2] = As[mb][k + 4];
                a[mt][3] = As[mb + 8][k + 4];
            }
            unsigned b[4][2];
#pragma unroll
            for (int nt = 0; nt < 4; nt++) {
                int nb = wn + nt * 8 + g;
                b[nt][0] = Bs[k][nb];
                b[nt][1] = Bs[k + 4][nb];
            }
#pragma unroll
            for (int mt = 0; mt < 2; mt++)
#pragma unroll
                for (int nt = 0; nt < 4; nt++) {
                    asm volatile(
                        "mma.sync.aligned.m16n8k8.row.col.f32.tf32.tf32.f32 "
                        "{%0,%1,%2,%3},{%4,%5,%6,%7},{%8,%9},{%0,%1,%2,%3};"
                        : "+f"(acc[mt][nt][0]), "+f"(acc[mt][nt][1]),
                          "+f"(acc[mt][nt][2]), "+f"(acc[mt][nt][3])
                        : "r"(a[mt][0]), "r"(a[mt][1]), "r"(a[mt][2]), "r"(a[mt][3]),
                          "r"(b[nt][0]), "r"(b[nt][1]));
                }
        }

        __syncthreads();
        if (kb + 1 < nk) {
            storeS();
            __syncthreads();
        }
    }

    // ---- epilogue ----
#pragma unroll
    for (int mt = 0; mt < 2; mt++) {
        int r0 = bm + wm + mt * 16 + g;
        int r1 = r0 + 8;
#pragma unroll
        for (int nt = 0; nt < 4; nt++) {
            int col = bn + wn + nt * 8 + 2 * t;
#pragma unroll
            for (int half = 0; half < 2; half++) {
                int row = half ? r1 : r0;
                if (row >= M) continue;
                float v0 = acc[mt][nt][half * 2 + 0];
                float v1 = acc[mt][nt][half * 2 + 1];
                if (bias) { v0 += bias[col]; v1 += bias[col + 1]; }
                if (MODE == 1) { v0 = v0 * sigf(v0); v1 = v1 * sigf(v1); }
                if (MODE == 2) {
                    v0 = res[(size_t)row * ldc + col] + v0;
                    v1 = res[(size_t)row * ldc + col + 1] + v1;
                }
                if (MODE == 3) {
                    v0 = res[(size_t)row * ldc + col] + 0.5f * v0;
                    v1 = res[(size_t)row * ldc + col + 1] + 0.5f * v1;
                }
                *(float2*)&C[(size_t)row * ldc + col] = make_float2(v0, v1);
            }
        }
    }
}

// ---------------- LayerNorm: one block per row, D=512, 256 threads ----------------
__global__ void __launch_bounds__(256) ln_kernel(
    const float* __restrict__ x, const float* __restrict__ s,
    const float* __restrict__ b, float* __restrict__ out)
{
    __shared__ float red[256];
    const int row = blockIdx.x;
    const float* xr = x + (size_t)row * Dd;
    const int tid = threadIdx.x;
    float v0 = xr[tid], v1 = xr[tid + 256];
    red[tid] = v0 + v1;
    __syncthreads();
    for (int o = 128; o > 0; o >>= 1) {
        if (tid < o) red[tid] += red[tid + o];
        __syncthreads();
    }
    float mean = red[0] * (1.0f / Dd);
    __syncthreads();
    float d0 = v0 - mean, d1 = v1 - mean;
    red[tid] = d0 * d0 + d1 * d1;
    __syncthreads();
    for (int o = 128; o > 0; o >>= 1) {
        if (tid < o) red[tid] += red[tid + o];
        __syncthreads();
    }
    float rstd = rsqrtf(red[0] * (1.0f / Dd) + EPSf);
    out[(size_t)row * Dd + tid]       = d0 * rstd * s[tid]       + b[tid];
    out[(size_t)row * Dd + tid + 256] = d1 * rstd * s[tid + 256] + b[tid + 256];
}

// ---------------- rel-pos attention scores ----------------
// S[b,h,t,s] = ((q+u)·k[s] + (q+v)·p[T-1-t+s]) * SCALE (rel_shift folded into index)
__global__ void __launch_bounds__(256) attn_scores(
    const float* __restrict__ Q, const float* __restrict__ Km,
    const float* __restrict__ Pm,
    const float* __restrict__ bu, const float* __restrict__ bvv,
    float* __restrict__ S)
{
    __shared__ __align__(16) float qu[32 * 64];
    __shared__ __align__(16) float qv[32 * 64];
    __shared__ __align__(16) float kt[32 * 64];
    __shared__ __align__(16) float pw[63 * 64];
    const int z = blockIdx.z;
    const int b = z >> 3, h = z & 7;
    const int t0 = blockIdx.y << 5, s0 = blockIdx.x << 5;
    const int tid = threadIdx.x;
    const float* bup = bu + h * 64;
    const float* bvp = bvv + h * 64;
    for (int i = tid; i < 32 * 64; i += 256) {
        int r = i >> 6, d = i & 63;
        float q = Q[(size_t)(b * Tn + t0 + r) * Dd + h * 64 + d];
        qu[i] = q + bup[d];
        qv[i] = q + bvp[d];
        kt[i] = Km[(size_t)(b * Tn + s0 + r) * Dd + h * 64 + d];
    }
    const int base = (Tn - 32) - t0 + s0;
    for (int i = tid; i < 63 * 64; i += 256) {
        int r = i >> 6, d = i & 63;
        pw[i] = Pm[(size_t)(base + r) * Dd + h * 64 + d];
    }
    __syncthreads();

    const int tx = tid & 15, ty = tid >> 4;
    const int tl = ty * 2, sl = tx * 2;
    const float4* qu4 = (const float4*)qu;
    const float4* qv4 = (const float4*)qv;
    const float4* kt4 = (const float4*)kt;
    const float4* pw4 = (const float4*)pw;
    const int pr = 31 - tl + sl;
    float a00 = 0.f, a01 = 0.f, a10 = 0.f, a11 = 0.f;
#pragma unroll
    for (int d4 = 0; d4 < 16; d4++) {
        float4 u0 = qu4[tl * 16 + d4];
        float4 u1 = qu4[(tl + 1) * 16 + d4];
        float4 v0 = qv4[tl * 16 + d4];
        float4 v1 = qv4[(tl + 1) * 16 + d4];
        float4 k0 = kt4[sl * 16 + d4];
        float4 k1 = kt4[(sl + 1) * 16 + d4];
        float4 pz = pw4[pr * 16 + d4];
        float4 pp = pw4[(pr + 1) * 16 + d4];
        float4 pm = pw4[(pr - 1) * 16 + d4];
        a00 += u0.x*k0.x + u0.y*k0.y + u0.z*k0.z + u0.w*k0.w
             + v0.x*pz.x + v0.y*pz.y + v0.z*pz.z + v0.w*pz.w;
        a01 += u0.x*k1.x + u0.y*k1.y + u0.z*k1.z + u0.w*k1.w
             + v0.x*pp.x + v0.y*pp.y + v0.z*pp.z + v0.w*pp.w;
        a10 += u1.x*k0.x + u1.y*k0.y + u1.z*k0.z + u1.w*k0.w
             + v1.x*pm.x + v1.y*pm.y + v1.z*pm.z + v1.w*pm.w;
        a11 += u1.x*k1.x + u1.y*k1.y + u1.z*k1.z + u1.w*k1.w
             + v1.x*pz.x + v1.y*pz.y + v1.z*pz.z + v1.w*pz.w;
    }
    float* Sp = S + ((size_t)z * Tn + (t0 + tl)) * Tn + (s0 + sl);
    Sp[0]      = a00 * SCALEf;
    Sp[1]      = a01 * SCALEf;
    Sp[Tn]     = a10 * SCALEf;
    Sp[Tn + 1] = a11 * SCALEf;
}

// ---------------- row softmax over T=1024 ----------------
__global__ void __launch_bounds__(256) softmax_kernel(float* __restrict__ S)
{
    __shared__ float red[256];
    float4* p = (float4*)(S + (size_t)blockIdx.x * Tn);
    const int tid = threadIdx.x;
    float4 x = p[tid];
    float m = fmaxf(fmaxf(x.x, x.y), fmaxf(x.z, x.w));
    red[tid] = m;
    __syncthreads();
    for (int o = 128; o > 0; o >>= 1) {
        if (tid < o) red[tid] = fmaxf(red[tid], red[tid + o]);
        __syncthreads();
    }
    m = red[0];
    __syncthreads();
    x.x = expf(x.x - m); x.y = expf(x.y - m); x.z = expf(x.z - m); x.w = expf(x.w - m);
    red[tid] = x.x + x.y + x.z + x.w;
    __syncthreads();
    for (int o = 128; o > 0; o >>= 1) {
        if (tid < o) red[tid] += red[tid + o];
        __syncthreads();
    }
    float inv = 1.0f / red[0];
    x.x *= inv; x.y *= inv; x.z *= inv; x.w *= inv;
    p[tid] = x;
}

// ---------------- GLU + transpose (B,T,2D) -> (B,D,T) ----------------
__global__ void __launch_bounds__(256) glu_kernel(const float* __restrict__ Y2,
                                                  float* __restrict__ CV)
{
    int idx = blockIdx.x * 256 + threadIdx.x;
    int t = idx & (Tn - 1);
    int bd = idx >> 10;
    int d = bd & (Dd - 1);
    int b = bd >> 9;
    size_t ybase = (size_t)(b * Tn + t) * (2 * Dd);
    float a = Y2[ybase + d];
    float g = Y2[ybase + Dd + d];
    CV[idx] = a * sigf(g);
}

// ---------------- depthwise conv K=31, pad 15 ----------------
__global__ void __launch_bounds__(128) dwconv_kernel(
    const float* __restrict__ CV, const float* __restrict__ w,
    const float* __restrict__ bias, float* __restrict__ out)
{
    __shared__ float sin_[128 + 30];
    __shared__ float sw[31];
    const int t0 = blockIdx.x * 128;
    const int d = blockIdx.y;
    const int b = blockIdx.z;
    const float* ip = CV + ((size_t)b * Dd + d) * Tn;
    const int tid = threadIdx.x;
    for (int i = tid; i < 158; i += 128) {
        int t = t0 - 15 + i;
        sin_[i] = (t >= 0 && t < Tn) ? ip[t] : 0.0f;
    }
    if (tid < 31) sw[tid] = w[d * KWn + tid];
    __syncthreads();
    float acc = bias[d];
#pragma unroll
    for (int k = 0; k < 31; k++) acc += sin_[tid + k] * sw[k];
    out[((size_t)b * Dd + d) * Tn + t0 + tid] = acc;
}

// ---------------- BatchNorm stats ----------------
__global__ void __launch_bounds__(256) bn_stats(const float* __restrict__ y)
{
    __shared__ float rs[256], rs2[256];
    const int d = blockIdx.x;
    const int tid = threadIdx.x;
    float s = 0.f, s2 = 0.f;
    for (int b = 0; b < Bn; b++) {
        const float* p = y + ((size_t)b * Dd + d) * Tn;
        for (int t = tid; t < Tn; t += 256) {
            float v = p[t];
            s += v;
            s2 += v * v;
        }
    }
    rs[tid] = s; rs2[tid] = s2;
    __syncthreads();
    for (int o = 128; o > 0; o >>= 1) {
        if (tid < o) { rs[tid] += rs[tid + o]; rs2[tid] += rs2[tid + o]; }
        __syncthreads();
    }
    if (tid == 0) {
        float mu = rs[0] * (1.0f / (Bn * Tn));
        float var = rs2[0] * (1.0f / (Bn * Tn)) - mu * mu;
        g_mu[d] = mu;
        g_rstd[d] = rsqrtf(var + EPSf);
    }
}

// ---------------- BN apply + SiLU + transpose (B,D,T) -> (B,T,D) ----------------
__global__ void __launch_bounds__(256) bn_apply(
    const float* __restrict__ y, const float* __restrict__ g,
    const float* __restrict__ bt, float* __restrict__ out)
{
    const int d = blockIdx.x;
    const int b = blockIdx.y;
    const int tid = threadIdx.x;
    float mu = g_mu[d], r = g_rstd[d], gg = g[d], bb = bt[d];
    const float* p = y + ((size_t)b * Dd + d) * Tn;
    for (int t = tid; t < Tn; t += 256) {
        float v = (p[t] - mu) * r * gg + bb;
        v = v * sigf(v);
        out[(size_t)(b * Tn + t) * Dd + d] = v;
    }
}

// ---------------- copy ----------------
__global__ void __launch_bounds__(256) copy_kernel(const float* __restrict__ in,
                                                   float* __restrict__ out, int n)
{
    int i = blockIdx.x * 256 + threadIdx.x;
    if (i < n) out[i] = in[i];
}

// ---------------- host-side launch helper ----------------
static void launch_tf32(int mode,
                        const float* A, int lda,
                        const float* W, int ldw,
                        const float* bias, const float* res,
                        float* C, int ldc,
                        int M, int N, int Kd)
{
    dim3 g(N / 64, (M + 127) / 128, 1);
    switch (mode) {
        case 0: tf32gemm<0, false><<<g, 256>>>(A, lda, W, ldw, bias, res, C, ldc, M, N, Kd); break;
        case 1: tf32gemm<1, false><<<g, 256>>>(A, lda, W, ldw, bias, res, C, ldc, M, N, Kd); break;
        case 2: tf32gemm<2, false><<<g, 256>>>(A, lda, W, ldw, bias, res, C, ldc, M, N, Kd); break;
        case 3: tf32gemm<3, false><<<g, 256>>>(A, lda, W, ldw, bias, res, C, ldc, M, N, Kd); break;
    }
}

extern "C" void kernel_launch(void* const* d_in, const int* in_sizes, int n_in,
                              void* d_out, int out_size)
{
    const float* in_x   = (const float*)d_in[0];
    const float* pos    = (const float*)d_in[1];
    const float* ln_s   = (const float*)d_in[2];
    const float* ln_b   = (const float*)d_in[3];
    const float* ff1_w1 = (const float*)d_in[4];
    const float* ff1_b1 = (const float*)d_in[5];
    const float* ff1_w2 = (const float*)d_in[6];
    const float* ff1_b2 = (const float*)d_in[7];
    const float* ff2_w1 = (const float*)d_in[8];
    const float* ff2_b1 = (const float*)d_in[9];
    const float* ff2_w2 = (const float*)d_in[10];
    const float* ff2_b2 = (const float*)d_in[11];
    const float* wq     = (const float*)d_in[12];
    const float* bq     = (const float*)d_in[13];
    const float* wk     = (const float*)d_in[14];
    const float* bk     = (const float*)d_in[15];
    const float* wv     = (const float*)d_in[16];
    const float* bv     = (const float*)d_in[17];
    const float* wp     = (const float*)d_in[18];
    const float* wo     = (const float*)d_in[19];
    const float* bo     = (const float*)d_in[20];
    const float* bias_u = (const float*)d_in[21];
    const float* bias_v = (const float*)d_in[22];
    const float* pw1_w  = (const float*)d_in[23];
    const float* pw1_b  = (const float*)d_in[24];
    const float* dw_w   = (const float*)d_in[25];
    const float* dw_b   = (const float*)d_in[26];
    const float* bn_g   = (const float*)d_in[27];
    const float* bn_b   = (const float*)d_in[28];
    const float* pw2_w  = (const float*)d_in[29];
    const float* pw2_b  = (const float*)d_in[30];
    (void)in_sizes; (void)n_in; (void)out_size;

    float *X, *Hb, *FF, *Qb, *Kb, *Vb, *Pb, *Sb, *CTX, *Y2, *CV, *CV2;
    cudaGetSymbolAddress((void**)&X,   g_X);
    cudaGetSymbolAddress((void**)&Hb,  g_H);
    cudaGetSymbolAddress((void**)&FF,  g_FF);
    cudaGetSymbolAddress((void**)&Qb,  g_Q);
    cudaGetSymbolAddress((void**)&Kb,  g_K);
    cudaGetSymbolAddress((void**)&Vb,  g_V);
    cudaGetSymbolAddress((void**)&Pb,  g_P);
    cudaGetSymbolAddress((void**)&Sb,  g_S);
    cudaGetSymbolAddress((void**)&CTX, g_CTX);
    cudaGetSymbolAddress((void**)&Y2,  g_Y2);
    cudaGetSymbolAddress((void**)&CV,  g_CV);
    cudaGetSymbolAddress((void**)&CV2, g_CV2);

    copy_kernel<<<(BTn * Dd) / 256, 256>>>(in_x, X, BTn * Dd);

    for (int l = 0; l < Ln; ++l) {
        const float* lnS = ln_s + (size_t)l * 5 * Dd;
        const float* lnB = ln_b + (size_t)l * 5 * Dd;

        // ---- macaron FFN 1 (half residual) ----
        ln_kernel<<<BTn, 256>>>(X, lnS, lnB, Hb);
        launch_tf32(1, Hb, Dd, ff1_w1 + (size_t)l * Dd * DFFd, DFFd,
                    ff1_b1 + (size_t)l * DFFd, nullptr, FF, DFFd, BTn, DFFd, Dd);
        launch_tf32(3, FF, DFFd, ff1_w2 + (size_t)l * DFFd * Dd, Dd,
                    ff1_b2 + (size_t)l * Dd, X, X, Dd, BTn, Dd, DFFd);

        // ---- rel-pos MHSA ----
        ln_kernel<<<BTn, 256>>>(X, lnS + Dd, lnB + Dd, Hb);
        launch_tf32(0, Hb, Dd, wq + (size_t)l * Dd * Dd, Dd,
                    bq + (size_t)l * Dd, nullptr, Qb, Dd, BTn, Dd, Dd);
        launch_tf32(0, Hb, Dd, wk + (size_t)l * Dd * Dd, Dd,
                    bk + (size_t)l * Dd, nullptr, Kb, Dd, BTn, Dd, Dd);
        launch_tf32(0, Hb, Dd, wv + (size_t)l * Dd * Dd, Dd,
                    bv + (size_t)l * Dd, nullptr, Vb, Dd, BTn, Dd, Dd);
        launch_tf32(0, pos, Dd, wp + (size_t)l * Dd * Dd, Dd,
                    nullptr, nullptr, Pb, Dd, Pn, Dd, Dd);

        attn_scores<<<dim3(Tn / 32, Tn / 32, Bn * Hn), 256>>>(
            Qb, Kb, Pb, bias_u + (size_t)l * Hn * DKn, bias_v + (size_t)l * Hn * DKn, Sb);
        softmax_kernel<<<Bn * Hn * Tn, 256>>>(Sb);

        // attn @ V, batched over all (b,h) in one launch
        tf32gemm<0, true><<<dim3(1, Tn / 128, Bn * Hn), 256>>>(
            Sb, Tn, Vb, Dd, nullptr, nullptr, CTX, Dd, Tn, DKn, Tn);

        launch_tf32(2, CTX, Dd, wo + (size_t)l * Dd * Dd, Dd,
                    bo + (size_t)l * Dd, X, X, Dd, BTn, Dd, Dd);

        // ---- conv module ----
        ln_kernel<<<BTn, 256>>>(X, lnS + 2 * Dd, lnB + 2 * Dd, Hb);
        launch_tf32(0, Hb, Dd, pw1_w + (size_t)l * Dd * 2 * Dd, 2 * Dd,
                    pw1_b + (size_t)l * 2 * Dd, nullptr, Y2, 2 * Dd, BTn, 2 * Dd, Dd);
        glu_kernel<<<(Bn * Dd * Tn) / 256, 256>>>(Y2, CV);
        dwconv_kernel<<<dim3(Tn / 128, Dd, Bn), 128>>>(
            CV, dw_w + (size_t)l * Dd * KWn, dw_b + (size_t)l * Dd, CV2);
        bn_stats<<<Dd, 256>>>(CV2);
        bn_apply<<<dim3(Dd, Bn), 256>>>(CV2, bn_g + (size_t)l * Dd, bn_b + (size_t)l * Dd, Hb);
        launch_tf32(2, Hb, Dd, pw2_w + (size_t)l * Dd * Dd, Dd,
                    pw2_b + (size_t)l * Dd, X, X, Dd, BTn, Dd, Dd);

        // ---- macaron FFN 2 (half residual) ----
        ln_kernel<<<BTn, 256>>>(X, lnS + 3 * Dd, lnB + 3 * Dd, Hb);
        launch_tf32(1, Hb, Dd, ff2_w1 + (size_t)l * Dd * DFFd, DFFd,
                    ff2_b1 + (size_t)l * DFFd, nullptr, FF, DFFd, BTn, DFFd, Dd);
        launch_tf32(3, FF, DFFd, ff2_w2 + (size_t)l * DFFd * Dd, Dd,
                    ff2_b2 + (size_t)l * Dd, X, X, Dd, BTn, Dd, DFFd);

        // ---- final per-layer LN ----
        float* outp = (l == Ln - 1) ? (float*)d_out : X;
        ln_kernel<<<BTn, 256>>>(X, lnS + 4 * Dd, lnB + 4 * Dd, outp);
    }
}

// round 7
// speedup vs baseline: 4.2035x; 2.8605x over previous
#include <cuda_runtime.h>
#include <math.h>

// ---------------- problem constants ----------------
constexpr int Dd   = 512;
constexpr int Hn   = 8;
constexpr int DFFd = 2048;
constexpr int KWn  = 31;
constexpr int Ln   = 2;
constexpr int Bn   = 4;
constexpr int Tn   = 1024;
constexpr int DKn  = 64;
constexpr int Pn   = 2 * Tn - 1;      // 2047
constexpr int BTn  = Bn * Tn;         // 4096
constexpr float EPSf   = 1e-5f;
constexpr float SCALEf = 0.125f;      // 1/sqrt(64)

// ---------------- device scratch (allocation-free) ----------------
__device__ float g_X  [BTn * Dd];
__device__ float g_H  [BTn * Dd];
__device__ float g_FF [BTn * DFFd];
__device__ float g_Q  [BTn * Dd];
__device__ float g_K  [BTn * Dd];
__device__ float g_V  [BTn * Dd];
__device__ float g_P  [Pn * Dd];
__device__ float g_S  [(size_t)Bn * Hn * Tn * Tn];  // 128 MB scores
__device__ float g_CTX[BTn * Dd];
__device__ float g_Y2 [BTn * 2 * Dd];
__device__ float g_CV [Bn * Dd * Tn];
__device__ float g_CV2[Bn * Dd * Tn];
__device__ float g_mu [Dd];
__device__ float g_rstd[Dd];

__device__ __forceinline__ float sigf(float x) { return 1.0f / (1.0f + expf(-x)); }

__device__ __forceinline__ unsigned f2tf32(float x) {
    unsigned u;
    asm("cvt.rna.tf32.f32 %0, %1;" : "=r"(u) : "f"(x));
    return u;
}

#define MMA_TF32(c0,c1,c2,c3,a0,a1,a2,a3,b0,b1)                              \
    asm volatile(                                                            \
        "mma.sync.aligned.m16n8k8.row.col.f32.tf32.tf32.f32 "                \
        "{%0,%1,%2,%3},{%4,%5,%6,%7},{%8,%9},{%0,%1,%2,%3};"                 \
        : "+f"(c0), "+f"(c1), "+f"(c2), "+f"(c3)                             \
        : "r"(a0), "r"(a1), "r"(a2), "r"(a3), "r"(b0), "r"(b1))

// =======================================================================
// TF32 tensor-core GEMM: C = epilogue(A (MxK, lda) @ W (KxN, ldw) + bias)
// Tile: BM=128, BN=64, BK=32. 256 threads = 8 warps (4 x 2), each warp
// computes 32x32 via 2x4 mma.sync.m16n8k8 fragments.
// MODE: 0 = (+bias), 1 = silu(+bias), 2 = res + (.), 3 = res + 0.5*(.)
// AV: blockIdx.z decodes (b,h) for the attn-prob @ V batched GEMM.
// =======================================================================
template <int MODE, bool AV>
__global__ void __launch_bounds__(256) tf32gemm(
    const float* __restrict__ A, int lda,
    const float* __restrict__ W, int ldw,
    const float* __restrict__ bias,
    const float* __restrict__ res,
    float* __restrict__ C, int ldc,
    int M, int N, int Kd)
{
    __shared__ unsigned As[128][36];   // [m][k], k < 32 + pad
    __shared__ unsigned Bs[32][72];    // [k][n], n < 64 + pad

    if (AV) {
        int z = blockIdx.z;                       // z = b*8 + h
        A += (size_t)z * Tn * Tn;                 // S[b][h] (T x T)
        size_t off = (size_t)(z >> 3) * Tn * Dd + (size_t)(z & 7) * DKn;
        W += off;
        C += off;
    }

    const int bm = blockIdx.y * 128, bn = blockIdx.x * 64;
    const int tid  = threadIdx.x;
    const int warp = tid >> 5, lane = tid & 31;
    const int g = lane >> 2, t = lane & 3;
    const int wm = (warp >> 1) * 32, wn = (warp & 1) * 32;

    float acc[2][4][4] = {};
    float4 pa[4];
    float4 pb[2];

    auto loadG = [&](int k0) {
#pragma unroll
        for (int i = 0; i < 4; i++) {
            int lin = i * 256 + tid;
            int row = lin >> 3, c4 = lin & 7;
            if (bm + row < M)
                pa[i] = *(const float4*)&A[(size_t)(bm + row) * lda + k0 + 4 * c4];
            else
                pa[i] = make_float4(0.f, 0.f, 0.f, 0.f);
        }
#pragma unroll
        for (int i = 0; i < 2; i++) {
            int lin = i * 256 + tid;
            int kr = lin >> 4, c4 = lin & 15;
            pb[i] = *(const float4*)&W[(size_t)(k0 + kr) * ldw + bn + 4 * c4];
        }
    };
    auto storeS = [&]() {
#pragma unroll
        for (int i = 0; i < 4; i++) {
            int lin = i * 256 + tid;
            int row = lin >> 3, c4 = lin & 7;
            unsigned* p = &As[row][4 * c4];
            p[0] = f2tf32(pa[i].x); p[1] = f2tf32(pa[i].y);
            p[2] = f2tf32(pa[i].z); p[3] = f2tf32(pa[i].w);
        }
#pragma unroll
        for (int i = 0; i < 2; i++) {
            int lin = i * 256 + tid;
            int kr = lin >> 4, c4 = lin & 15;
            unsigned* p = &Bs[kr][4 * c4];
            p[0] = f2tf32(pb[i].x); p[1] = f2tf32(pb[i].y);
            p[2] = f2tf32(pb[i].z); p[3] = f2tf32(pb[i].w);
        }
    };

    const int nk = Kd >> 5;
    loadG(0);
    storeS();
    __syncthreads();

    for (int kb = 0; kb < nk; kb++) {
        if (kb + 1 < nk) loadG((kb + 1) * 32);

#pragma unroll
        for (int kt = 0; kt < 4; kt++) {
            const int k = kt * 8 + t;
            unsigned a[2][4];
#pragma unroll
            for (int mt = 0; mt < 2; mt++) {
                int mb = wm + mt * 16 + g;
                a[mt][0] = As[mb][k];
                a[mt][1] = As[mb + 8][k];
                a[mt][2] = As[mb][k + 4];
                a[mt][3] = As[mb + 8][k + 4];
            }
            unsigned b[4][2];
#pragma unroll
            for (int nt = 0; nt < 4; nt++) {
                int nb = wn + nt * 8 + g;
                b[nt][0] = Bs[k][nb];
                b[nt][1] = Bs[k + 4][nb];
            }
#pragma unroll
            for (int mt = 0; mt < 2; mt++)
#pragma unroll
                for (int nt = 0; nt < 4; nt++)
                    MMA_TF32(acc[mt][nt][0], acc[mt][nt][1], acc[mt][nt][2], acc[mt][nt][3],
                             a[mt][0], a[mt][1], a[mt][2], a[mt][3],
                             b[nt][0], b[nt][1]);
        }

        __syncthreads();
        if (kb + 1 < nk) {
            storeS();
            __syncthreads();
        }
    }

#pragma unroll
    for (int mt = 0; mt < 2; mt++) {
        int r0 = bm + wm + mt * 16 + g;
        int r1 = r0 + 8;
#pragma unroll
        for (int nt = 0; nt < 4; nt++) {
            int col = bn + wn + nt * 8 + 2 * t;
#pragma unroll
            for (int half = 0; half < 2; half++) {
                int row = half ? r1 : r0;
                if (row >= M) continue;
                float v0 = acc[mt][nt][half * 2 + 0];
                float v1 = acc[mt][nt][half * 2 + 1];
                if (bias) { v0 += bias[col]; v1 += bias[col + 1]; }
                if (MODE == 1) { v0 = v0 * sigf(v0); v1 = v1 * sigf(v1); }
                if (MODE == 2) {
                    v0 = res[(size_t)row * ldc + col] + v0;
                    v1 = res[(size_t)row * ldc + col + 1] + v1;
                }
                if (MODE == 3) {
                    v0 = res[(size_t)row * ldc + col] + 0.5f * v0;
                    v1 = res[(size_t)row * ldc + col + 1] + 0.5f * v1;
                }
                *(float2*)&C[(size_t)row * ldc + col] = make_float2(v0, v1);
            }
        }
    }
}

// ---------------- LayerNorm: 128 threads, float4, warp shuffles ----------------
__global__ void __launch_bounds__(128) ln_kernel(
    const float* __restrict__ x, const float* __restrict__ s,
    const float* __restrict__ b, float* __restrict__ out)
{
    __shared__ float red[8];
    const int row = blockIdx.x;
    const int tid = threadIdx.x;
    const int lane = tid & 31, wid = tid >> 5;
    float4 v = ((const float4*)(x + (size_t)row * Dd))[tid];

    float s1 = v.x + v.y + v.z + v.w;
#pragma unroll
    for (int o = 16; o > 0; o >>= 1) s1 += __shfl_xor_sync(0xffffffffu, s1, o);
    if (lane == 0) red[wid] = s1;
    __syncthreads();
    float mean = (red[0] + red[1] + red[2] + red[3]) * (1.0f / Dd);

    float4 d;
    d.x = v.x - mean; d.y = v.y - mean; d.z = v.z - mean; d.w = v.w - mean;
    float s2 = d.x * d.x + d.y * d.y + d.z * d.z + d.w * d.w;
#pragma unroll
    for (int o = 16; o > 0; o >>= 1) s2 += __shfl_xor_sync(0xffffffffu, s2, o);
    if (lane == 0) red[4 + wid] = s2;
    __syncthreads();
    float rstd = rsqrtf((red[4] + red[5] + red[6] + red[7]) * (1.0f / Dd) + EPSf);

    float4 sc = ((const float4*)s)[tid];
    float4 bc = ((const float4*)b)[tid];
    float4 o4;
    o4.x = d.x * rstd * sc.x + bc.x;
    o4.y = d.y * rstd * sc.y + bc.y;
    o4.z = d.z * rstd * sc.z + bc.z;
    o4.w = d.w * rstd * sc.w + bc.w;
    ((float4*)(out + (size_t)row * Dd))[tid] = o4;
}

// =======================================================================
// rel-pos attention scores on tensor cores.
// S[b,h,t,s] = ((q+u)·k[s] + (q+v)·p[T-1-t+s]) * SCALE
// Decomposed: q·k (MMA) + q·p (MMA) + u·k[s] (rank-1 col vec) + v·p[pr]
// (rank-1 vec). pw = 63-row p-window + zero row; rel-shift folded into
// the epilogue index pr = 31 - t + s.
// =======================================================================
__global__ void __launch_bounds__(256) attn_scores(
    const float* __restrict__ Q, const float* __restrict__ Km,
    const float* __restrict__ Pm,
    const float* __restrict__ bu, const float* __restrict__ bvv,
    float* __restrict__ S)
{
    __shared__ unsigned qs[32][66], kt[32][66], pw[64][66];
    __shared__ float C1[32][33];
    __shared__ float C2[32][68];
    __shared__ float uk[32], vp[64];
    __shared__ float us[64], vs[64];

    const int z = blockIdx.z;
    const int b = z >> 3, h = z & 7;
    const int t0 = blockIdx.y << 5, s0 = blockIdx.x << 5;
    const int tid = threadIdx.x;

    if (tid < 16)
        ((float4*)us)[tid] = ((const float4*)(bu + h * 64))[tid];
    else if (tid < 32)
        ((float4*)vs)[tid - 16] = ((const float4*)(bvv + h * 64))[tid - 16];

    // load q and k (32 rows x 64 cols each) as tf32
    for (int i = tid; i < 512; i += 256) {
        int r = i >> 4, c = (i & 15) * 4;
        float4 q4 = *(const float4*)&Q[(size_t)(b * Tn + t0 + r) * Dd + h * 64 + c];
        qs[r][c + 0] = f2tf32(q4.x);
        qs[r][c + 1] = f2tf32(q4.y);
        qs[r][c + 2] = f2tf32(q4.z);
        qs[r][c + 3] = f2tf32(q4.w);
        float4 k4 = *(const float4*)&Km[(size_t)(b * Tn + s0 + r) * Dd + h * 64 + c];
        kt[r][c + 0] = f2tf32(k4.x);
        kt[r][c + 1] = f2tf32(k4.y);
        kt[r][c + 2] = f2tf32(k4.z);
        kt[r][c + 3] = f2tf32(k4.w);
    }
    // p window: rows 0..62 real, row 63 zero
    const int base = (Tn - 32) - t0 + s0;     // in [0, P-63]
    for (int i = tid; i < 1024; i += 256) {
        int r = i >> 4, c = (i & 15) * 4;
        if (r < 63) {
            float4 p4 = *(const float4*)&Pm[(size_t)(base + r) * Dd + h * 64 + c];
            pw[r][c + 0] = f2tf32(p4.x);
            pw[r][c + 1] = f2tf32(p4.y);
            pw[r][c + 2] = f2tf32(p4.z);
            pw[r][c + 3] = f2tf32(p4.w);
        } else {
            pw[r][c + 0] = 0u; pw[r][c + 1] = 0u; pw[r][c + 2] = 0u; pw[r][c + 3] = 0u;
        }
    }
    __syncthreads();

    const int warp = tid >> 5, lane = tid & 31;
    const int g = lane >> 2, t = lane & 3;
    const int mw  = (warp >> 2) * 16;          // m-tile: warps 0-3 -> 0, 4-7 -> 16
    const int nwA = (warp & 3) * 8;            // 16x8 tile of q@k^T
    const int nw2 = (warp & 3) * 16;           // 16x16 slab of q@pw^T

    float c1r[4] = {};
    float e[2][4] = {};
#pragma unroll
    for (int k0 = 0; k0 < 64; k0 += 8) {
        const int k = k0 + t;
        unsigned a0 = qs[mw + g][k],     a1 = qs[mw + 8 + g][k];
        unsigned a2 = qs[mw + g][k + 4], a3 = qs[mw + 8 + g][k + 4];
        unsigned b0 = kt[nwA + g][k],    b1 = kt[nwA + g][k + 4];
        MMA_TF32(c1r[0], c1r[1], c1r[2], c1r[3], a0, a1, a2, a3, b0, b1);
#pragma unroll
        for (int nt = 0; nt < 2; nt++) {
            int nb = nw2 + nt * 8 + g;
            unsigned p0 = pw[nb][k], p1 = pw[nb][k + 4];
            MMA_TF32(e[nt][0], e[nt][1], e[nt][2], e[nt][3], a0, a1, a2, a3, p0, p1);
        }
    }
    C1[mw + g][nwA + 2 * t]         = c1r[0];
    C1[mw + g][nwA + 2 * t + 1]     = c1r[1];
    C1[mw + 8 + g][nwA + 2 * t]     = c1r[2];
    C1[mw + 8 + g][nwA + 2 * t + 1] = c1r[3];
#pragma unroll
    for (int nt = 0; nt < 2; nt++) {
        int nb = nw2 + nt * 8;
        C2[mw + g][nb + 2 * t]         = e[nt][0];
        C2[mw + g][nb + 2 * t + 1]     = e[nt][1];
        C2[mw + 8 + g][nb + 2 * t]     = e[nt][2];
        C2[mw + 8 + g][nb + 2 * t + 1] = e[nt][3];
    }

    // rank-1 bias corrections: uk[s] = u . k[s],  vp[r] = v . p[r]
    if (tid < 32) {
        float s = 0.f;
#pragma unroll 8
        for (int d = 0; d < 64; d++) s += us[d] * __uint_as_float(kt[tid][d]);
        uk[tid] = s;
    } else if (tid < 96) {
        int r = tid - 32;
        float s = 0.f;
#pragma unroll 8
        for (int d = 0; d < 64; d++) s += vs[d] * __uint_as_float(pw[r][d]);
        vp[r] = s;
    }
    __syncthreads();

    // epilogue: combine with rel-shift, write coalesced float4
    const int tl = tid >> 3, sl = (tid & 7) * 4;
    const int pr = 31 - tl + sl;
    float4 o4;
    o4.x = (C1[tl][sl + 0] + uk[sl + 0] + C2[tl][pr + 0] + vp[pr + 0]) * SCALEf;
    o4.y = (C1[tl][sl + 1] + uk[sl + 1] + C2[tl][pr + 1] + vp[pr + 1]) * SCALEf;
    o4.z = (C1[tl][sl + 2] + uk[sl + 2] + C2[tl][pr + 2] + vp[pr + 2]) * SCALEf;
    o4.w = (C1[tl][sl + 3] + uk[sl + 3] + C2[tl][pr + 3] + vp[pr + 3]) * SCALEf;
    *(float4*)&S[((size_t)z * Tn + (t0 + tl)) * Tn + (s0 + sl)] = o4;
}

// ---------------- row softmax over T=1024 ----------------
__global__ void __launch_bounds__(256) softmax_kernel(float* __restrict__ S)
{
    __shared__ float red[256];
    float4* p = (float4*)(S + (size_t)blockIdx.x * Tn);
    const int tid = threadIdx.x;
    float4 x = p[tid];
    float m = fmaxf(fmaxf(x.x, x.y), fmaxf(x.z, x.w));
    red[tid] = m;
    __syncthreads();
    for (int o = 128; o > 0; o >>= 1) {
        if (tid < o) red[tid] = fmaxf(red[tid], red[tid + o]);
        __syncthreads();
    }
    m = red[0];
    __syncthreads();
    x.x = expf(x.x - m); x.y = expf(x.y - m); x.z = expf(x.z - m); x.w = expf(x.w - m);
    red[tid] = x.x + x.y + x.z + x.w;
    __syncthreads();
    for (int o = 128; o > 0; o >>= 1) {
        if (tid < o) red[tid] += red[tid + o];
        __syncthreads();
    }
    float inv = 1.0f / red[0];
    x.x *= inv; x.y *= inv; x.z *= inv; x.w *= inv;
    p[tid] = x;
}

// ---------------- GLU + transpose (B,T,2D) -> (B,D,T), tiled ----------------
__global__ void __launch_bounds__(256) glu_tr(const float* __restrict__ Y2,
                                              float* __restrict__ CV)
{
    __shared__ float tile[32][33];
    const int b = blockIdx.z;
    const int d0 = blockIdx.y * 32, t0 = blockIdx.x * 32;
    const int tid = threadIdx.x;
    const int rr = tid >> 5, cc = tid & 31;
#pragma unroll
    for (int i = 0; i < 4; i++) {
        int tl = rr + i * 8;
        size_t base = (size_t)(b * Tn + t0 + tl) * (2 * Dd) + d0 + cc;
        float a = Y2[base];
        float g = Y2[base + Dd];
        tile[tl][cc] = a * sigf(g);
    }
    __syncthreads();
#pragma unroll
    for (int i = 0; i < 4; i++) {
        int dl = rr + i * 8;
        CV[((size_t)b * Dd + d0 + dl) * Tn + t0 + cc] = tile[cc][dl];
    }
}

// ---------------- depthwise conv K=31, pad 15 ----------------
__global__ void __launch_bounds__(128) dwconv_kernel(
    const float* __restrict__ CV, const float* __restrict__ w,
    const float* __restrict__ bias, float* __restrict__ out)
{
    __shared__ float sin_[128 + 30];
    __shared__ float sw[31];
    const int t0 = blockIdx.x * 128;
    const int d = blockIdx.y;
    const int b = blockIdx.z;
    const float* ip = CV + ((size_t)b * Dd + d) * Tn;
    const int tid = threadIdx.x;
    for (int i = tid; i < 158; i += 128) {
        int t = t0 - 15 + i;
        sin_[i] = (t >= 0 && t < Tn) ? ip[t] : 0.0f;
    }
    if (tid < 31) sw[tid] = w[d * KWn + tid];
    __syncthreads();
    float acc = bias[d];
#pragma unroll
    for (int k = 0; k < 31; k++) acc += sin_[tid + k] * sw[k];
    out[((size_t)b * Dd + d) * Tn + t0 + tid] = acc;
}

// ---------------- BatchNorm stats ----------------
__global__ void __launch_bounds__(256) bn_stats(const float* __restrict__ y)
{
    __shared__ float rs[256], rs2[256];
    const int d = blockIdx.x;
    const int tid = threadIdx.x;
    float s = 0.f, s2 = 0.f;
    for (int b = 0; b < Bn; b++) {
        const float* p = y + ((size_t)b * Dd + d) * Tn;
        for (int t = tid; t < Tn; t += 256) {
            float v = p[t];
            s += v;
            s2 += v * v;
        }
    }
    rs[tid] = s; rs2[tid] = s2;
    __syncthreads();
    for (int o = 128; o > 0; o >>= 1) {
        if (tid < o) { rs[tid] += rs[tid + o]; rs2[tid] += rs2[tid + o]; }
        __syncthreads();
    }
    if (tid == 0) {
        float mu = rs[0] * (1.0f / (Bn * Tn));
        float var = rs2[0] * (1.0f / (Bn * Tn)) - mu * mu;
        g_mu[d] = mu;
        g_rstd[d] = rsqrtf(var + EPSf);
    }
}

// ---------------- BN apply + SiLU + transpose (B,D,T) -> (B,T,D), tiled ----------------
__global__ void __launch_bounds__(256) bn_tr(
    const float* __restrict__ y, const float* __restrict__ g,
    const float* __restrict__ bt, float* __restrict__ out)
{
    __shared__ float tile[32][33];
    const int b = blockIdx.z;
    const int d0 = blockIdx.y * 32, t0 = blockIdx.x * 32;
    const int tid = threadIdx.x;
    const int rr = tid >> 5, cc = tid & 31;
#pragma unroll
    for (int i = 0; i < 4; i++) {
        int dl = rr + i * 8;
        int d = d0 + dl;
        float v = y[((size_t)b * Dd + d) * Tn + t0 + cc];
        v = (v - g_mu[d]) * g_rstd[d] * g[d] + bt[d];
        v = v * sigf(v);
        tile[dl][cc] = v;
    }
    __syncthreads();
#pragma unroll
    for (int i = 0; i < 4; i++) {
        int tl = rr + i * 8;
        out[(size_t)(b * Tn + t0 + tl) * Dd + d0 + cc] = tile[cc][tl];
    }
}

// ---------------- copy ----------------
__global__ void __launch_bounds__(256) copy_kernel(const float* __restrict__ in,
                                                   float* __restrict__ out, int n)
{
    int i = blockIdx.x * 256 + threadIdx.x;
    if (i < n) out[i] = in[i];
}

// ---------------- host-side launch helper ----------------
static void launch_tf32(int mode,
                        const float* A, int lda,
                        const float* W, int ldw,
                        const float* bias, const float* res,
                        float* C, int ldc,
                        int M, int N, int Kd)
{
    dim3 g(N / 64, (M + 127) / 128, 1);
    switch (mode) {
        case 0: tf32gemm<0, false><<<g, 256>>>(A, lda, W, ldw, bias, res, C, ldc, M, N, Kd); break;
        case 1: tf32gemm<1, false><<<g, 256>>>(A, lda, W, ldw, bias, res, C, ldc, M, N, Kd); break;
        case 2: tf32gemm<2, false><<<g, 256>>>(A, lda, W, ldw, bias, res, C, ldc, M, N, Kd); break;
        case 3: tf32gemm<3, false><<<g, 256>>>(A, lda, W, ldw, bias, res, C, ldc, M, N, Kd); break;
    }
}

extern "C" void kernel_launch(void* const* d_in, const int* in_sizes, int n_in,
                              void* d_out, int out_size)
{
    const float* in_x   = (const float*)d_in[0];
    const float* pos    = (const float*)d_in[1];
    const float* ln_s   = (const float*)d_in[2];
    const float* ln_b   = (const float*)d_in[3];
    const float* ff1_w1 = (const float*)d_in[4];
    const float* ff1_b1 = (const float*)d_in[5];
    const float* ff1_w2 = (const float*)d_in[6];
    const float* ff1_b2 = (const float*)d_in[7];
    const float* ff2_w1 = (const float*)d_in[8];
    const float* ff2_b1 = (const float*)d_in[9];
    const float* ff2_w2 = (const float*)d_in[10];
    const float* ff2_b2 = (const float*)d_in[11];
    const float* wq     = (const float*)d_in[12];
    const float* bq     = (const float*)d_in[13];
    const float* wk     = (const float*)d_in[14];
    const float* bk     = (const float*)d_in[15];
    const float* wv     = (const float*)d_in[16];
    const float* bv     = (const float*)d_in[17];
    const float* wp     = (const float*)d_in[18];
    const float* wo     = (const float*)d_in[19];
    const float* bo     = (const float*)d_in[20];
    const float* bias_u = (const float*)d_in[21];
    const float* bias_v = (const float*)d_in[22];
    const float* pw1_w  = (const float*)d_in[23];
    const float* pw1_b  = (const float*)d_in[24];
    const float* dw_w   = (const float*)d_in[25];
    const float* dw_b   = (const float*)d_in[26];
    const float* bn_g   = (const float*)d_in[27];
    const float* bn_b   = (const float*)d_in[28];
    const float* pw2_w  = (const float*)d_in[29];
    const float* pw2_b  = (const float*)d_in[30];
    (void)in_sizes; (void)n_in; (void)out_size;

    float *X, *Hb, *FF, *Qb, *Kb, *Vb, *Pb, *Sb, *CTX, *Y2, *CV, *CV2;
    cudaGetSymbolAddress((void**)&X,   g_X);
    cudaGetSymbolAddress((void**)&Hb,  g_H);
    cudaGetSymbolAddress((void**)&FF,  g_FF);
    cudaGetSymbolAddress((void**)&Qb,  g_Q);
    cudaGetSymbolAddress((void**)&Kb,  g_K);
    cudaGetSymbolAddress((void**)&Vb,  g_V);
    cudaGetSymbolAddress((void**)&Pb,  g_P);
    cudaGetSymbolAddress((void**)&Sb,  g_S);
    cudaGetSymbolAddress((void**)&CTX, g_CTX);
    cudaGetSymbolAddress((void**)&Y2,  g_Y2);
    cudaGetSymbolAddress((void**)&CV,  g_CV);
    cudaGetSymbolAddress((void**)&CV2, g_CV2);

    copy_kernel<<<(BTn * Dd) / 256, 256>>>(in_x, X, BTn * Dd);

    for (int l = 0; l < Ln; ++l) {
        const float* lnS = ln_s + (size_t)l * 5 * Dd;
        const float* lnB = ln_b + (size_t)l * 5 * Dd;

        // ---- macaron FFN 1 (half residual) ----
        ln_kernel<<<BTn, 128>>>(X, lnS, lnB, Hb);
        launch_tf32(1, Hb, Dd, ff1_w1 + (size_t)l * Dd * DFFd, DFFd,
                    ff1_b1 + (size_t)l * DFFd, nullptr, FF, DFFd, BTn, DFFd, Dd);
        launch_tf32(3, FF, DFFd, ff1_w2 + (size_t)l * DFFd * Dd, Dd,
                    ff1_b2 + (size_t)l * Dd, X, X, Dd, BTn, Dd, DFFd);

        // ---- rel-pos MHSA ----
        ln_kernel<<<BTn, 128>>>(X, lnS + Dd, lnB + Dd, Hb);
        launch_tf32(0, Hb, Dd, wq + (size_t)l * Dd * Dd, Dd,
                    bq + (size_t)l * Dd, nullptr, Qb, Dd, BTn, Dd, Dd);
        launch_tf32(0, Hb, Dd, wk + (size_t)l * Dd * Dd, Dd,
                    bk + (size_t)l * Dd, nullptr, Kb, Dd, BTn, Dd, Dd);
        launch_tf32(0, Hb, Dd, wv + (size_t)l * Dd * Dd, Dd,
                    bv + (size_t)l * Dd, nullptr, Vb, Dd, BTn, Dd, Dd);
        launch_tf32(0, pos, Dd, wp + (size_t)l * Dd * Dd, Dd,
                    nullptr, nullptr, Pb, Dd, Pn, Dd, Dd);

        attn_scores<<<dim3(Tn / 32, Tn / 32, Bn * Hn), 256>>>(
            Qb, Kb, Pb, bias_u + (size_t)l * Hn * DKn, bias_v + (size_t)l * Hn * DKn, Sb);
        softmax_kernel<<<Bn * Hn * Tn, 256>>>(Sb);

        tf32gemm<0, true><<<dim3(1, Tn / 128, Bn * Hn), 256>>>(
            Sb, Tn, Vb, Dd, nullptr, nullptr, CTX, Dd, Tn, DKn, Tn);

        launch_tf32(2, CTX, Dd, wo + (size_t)l * Dd * Dd, Dd,
                    bo + (size_t)l * Dd, X, X, Dd, BTn, Dd, Dd);

        // ---- conv module ----
        ln_kernel<<<BTn, 128>>>(X, lnS + 2 * Dd, lnB + 2 * Dd, Hb);
        launch_tf32(0, Hb, Dd, pw1_w + (size_t)l * Dd * 2 * Dd, 2 * Dd,
                    pw1_b + (size_t)l * 2 * Dd, nullptr, Y2, 2 * Dd, BTn, 2 * Dd, Dd);
        glu_tr<<<dim3(Tn / 32, Dd / 32, Bn), 256>>>(Y2, CV);
        dwconv_kernel<<<dim3(Tn / 128, Dd, Bn), 128>>>(
            CV, dw_w + (size_t)l * Dd * KWn, dw_b + (size_t)l * Dd, CV2);
        bn_stats<<<Dd, 256>>>(CV2);
        bn_tr<<<dim3(Tn / 32, Dd / 32, Bn), 256>>>(
            CV2, bn_g + (size_t)l * Dd, bn_b + (size_t)l * Dd, Hb);
        launch_tf32(2, Hb, Dd, pw2_w + (size_t)l * Dd * Dd, Dd,
                    pw2_b + (size_t)l * Dd, X, X, Dd, BTn, Dd, Dd);

        // ---- macaron FFN 2 (half residual) ----
        ln_kernel<<<BTn, 128>>>(X, lnS + 3 * Dd, lnB + 3 * Dd, Hb);
        launch_tf32(1, Hb, Dd, ff2_w1 + (size_t)l * Dd * DFFd, DFFd,
                    ff2_b1 + (size_t)l * DFFd, nullptr, FF, DFFd, BTn, DFFd, Dd);
        launch_tf32(3, FF, DFFd, ff2_w2 + (size_t)l * DFFd * Dd, Dd,
                    ff2_b2 + (size_t)l * Dd, X, X, Dd, BTn, Dd, DFFd);

        // ---- final per-layer LN ----
        float* outp = (l == Ln - 1) ? (float*)d_out : X;
        ln_kernel<<<BTn, 128>>>(X, lnS + 4 * Dd, lnB + 4 * Dd, outp);
    }
}

// round 8
// speedup vs baseline: 4.8538x; 1.1547x over previous
#include <cuda_runtime.h>
#include <math.h>

// ---------------- problem constants ----------------
constexpr int Dd   = 512;
constexpr int Hn   = 8;
constexpr int DFFd = 2048;
constexpr int KWn  = 31;
constexpr int Ln   = 2;
constexpr int Bn   = 4;
constexpr int Tn   = 1024;
constexpr int DKn  = 64;
constexpr int Pn   = 2 * Tn - 1;      // 2047
constexpr int BTn  = Bn * Tn;         // 4096
constexpr float EPSf   = 1e-5f;
constexpr float SCALEf = 0.125f;      // 1/sqrt(64)

// rounded-weight scratch layout (floats)
constexpr size_t OFF_FF1W1 = 0;
constexpr size_t OFF_FF1W2 = OFF_FF1W1 + (size_t)Ln * Dd * DFFd;
constexpr size_t OFF_FF2W1 = OFF_FF1W2 + (size_t)Ln * DFFd * Dd;
constexpr size_t OFF_FF2W2 = OFF_FF2W1 + (size_t)Ln * Dd * DFFd;
constexpr size_t OFF_WQ    = OFF_FF2W2 + (size_t)Ln * DFFd * Dd;
constexpr size_t OFF_WK    = OFF_WQ + (size_t)Ln * Dd * Dd;
constexpr size_t OFF_WV    = OFF_WK + (size_t)Ln * Dd * Dd;
constexpr size_t OFF_WO    = OFF_WV + (size_t)Ln * Dd * Dd;
constexpr size_t OFF_WP    = OFF_WO + (size_t)Ln * Dd * Dd;
constexpr size_t OFF_PW1   = OFF_WP + (size_t)Ln * Dd * Dd;
constexpr size_t OFF_PW2   = OFF_PW1 + (size_t)Ln * Dd * 2 * Dd;
constexpr size_t WR_TOTAL  = OFF_PW2 + (size_t)Ln * Dd * Dd;

// ---------------- device scratch (allocation-free) ----------------
__device__ float g_X  [BTn * Dd];
__device__ float g_H  [BTn * Dd];
__device__ float g_FF [BTn * DFFd];
__device__ float g_Q  [BTn * Dd];
__device__ float g_K  [BTn * Dd];
__device__ float g_V  [BTn * Dd];
__device__ float g_P  [Pn * Dd];
__device__ float g_S  [(size_t)Bn * Hn * Tn * Tn];  // 128 MB scores
__device__ float g_CTX[BTn * Dd];
__device__ float g_Y2 [BTn * 2 * Dd];
__device__ float g_CV [Bn * Dd * Tn];
__device__ float g_CV2[Bn * Dd * Tn];
__device__ float g_mu [Dd];
__device__ float g_rstd[Dd];
__device__ float g_WR [WR_TOTAL];          // tf32-rounded weights
__device__ float g_PosR[Pn * Dd];          // tf32-rounded pos

__device__ __forceinline__ float sigf(float x) { return 1.0f / (1.0f + expf(-x)); }

__device__ __forceinline__ unsigned f2tf32(float x) {
    unsigned u;
    asm("cvt.rna.tf32.f32 %0, %1;" : "=r"(u) : "f"(x));
    return u;
}
__device__ __forceinline__ float rnd_tf32(float x) { return __uint_as_float(f2tf32(x)); }

#define MMA_TF32(c0,c1,c2,c3,a0,a1,a2,a3,b0,b1)                              \
    asm volatile(                                                            \
        "mma.sync.aligned.m16n8k8.row.col.f32.tf32.tf32.f32 "                \
        "{%0,%1,%2,%3},{%4,%5,%6,%7},{%8,%9},{%0,%1,%2,%3};"                 \
        : "+f"(c0), "+f"(c1), "+f"(c2), "+f"(c3)                             \
        : "r"(a0), "r"(a1), "r"(a2), "r"(a3), "r"(b0), "r"(b1))

__device__ __forceinline__ void cpa16(unsigned dst, const void* src, int szbytes) {
    asm volatile("cp.async.cg.shared.global [%0], [%1], 16, %2;"
                 :: "r"(dst), "l"(src), "r"(szbytes));
}

// =======================================================================
// TF32 tensor-core GEMM, cp.async double-buffered, XOR-swizzled smem.
// C = epilogue(A (MxK, lda) @ W (KxN, ldw) + bias)
// Tile: BM=128, BN=64, BK=32. 256 threads = 8 warps (4x2), each warp 32x32.
// Inputs MUST be tf32-pre-rounded floats (cp.async truncation is lossless).
// MODE: 0 = (+bias, rnd), 1 = silu(+bias, rnd), 2 = res + (.), 3 = res + 0.5*(.)
// AV: blockIdx.z decodes (b,h) for the attn-prob @ V batched GEMM.
// =======================================================================
template <int MODE, bool AV>
__global__ void __launch_bounds__(256) tf32gemm(
    const float* __restrict__ A, int lda,
    const float* __restrict__ W, int ldw,
    const float* __restrict__ bias,
    const float* __restrict__ res,
    float* __restrict__ C, int ldc,
    int M, int N, int Kd)
{
    // A[stage][row][col']: col' = ((k>>2)^(row&7))*4 + (k&3)
    // B[stage][k][col']:   col' = ((n>>2)^(2*(k&3)))*4 + (n&3)
    __shared__ unsigned As[2][128][32];
    __shared__ unsigned Bs[2][32][64];

    if (AV) {
        int z = blockIdx.z;                       // z = b*8 + h
        A += (size_t)z * Tn * Tn;                 // S[b][h] (T x T)
        size_t off = (size_t)(z >> 3) * Tn * Dd + (size_t)(z & 7) * DKn;
        W += off;
        C += off;
    }

    const int bm = blockIdx.y * 128, bn = blockIdx.x * 64;
    const int tid  = threadIdx.x;
    const int warp = tid >> 5, lane = tid & 31;
    const int g = lane >> 2, t = lane & 3;
    const int wm = (warp >> 1) * 32, wn = (warp & 1) * 32;

    unsigned asBase = (unsigned)__cvta_generic_to_shared(&As[0][0][0]);
    unsigned bsBase = (unsigned)__cvta_generic_to_shared(&Bs[0][0][0]);

    auto loadTile = [&](int stage, int k0) {
#pragma unroll
        for (int i = 0; i < 4; i++) {
            int lin = i * 256 + tid;
            int row = lin >> 3, ck = lin & 7;           // 8 chunks of 16B per row
            int pc = ck ^ (row & 7);
            unsigned dst = asBase + (((stage << 7) + row) * 32 + pc * 4) * 4;
            const float* src = A + (size_t)(bm + row) * lda + k0 + ck * 4;
            cpa16(dst, src, (bm + row < M) ? 16 : 0);
        }
#pragma unroll
        for (int i = 0; i < 2; i++) {
            int lin = i * 256 + tid;
            int kr = lin >> 4, c4 = lin & 15;           // 16 chunks per row
            int pc = c4 ^ (2 * (kr & 3));
            unsigned dst = bsBase + (((stage << 5) + kr) * 64 + pc * 4) * 4;
            const float* src = W + (size_t)(k0 + kr) * ldw + bn + c4 * 4;
            cpa16(dst, src, 16);
        }
        asm volatile("cp.async.commit_group;");
    };

    float acc[2][4][4] = {};

    // per-warp precomputed B fragment columns (independent of kt)
    int colB[4];
#pragma unroll
    for (int nt = 0; nt < 4; nt++) {
        int nb = wn + nt * 8 + g;
        colB[nt] = (((nb >> 2) ^ (2 * t)) << 2) | (nb & 3);
    }
    const int rA0 = wm + g, rA1 = wm + 16 + g;

    const int nk = Kd >> 5;
    loadTile(0, 0);

    for (int kb = 0; kb < nk; kb++) {
        const int cur = kb & 1;
        if (kb + 1 < nk) {
            loadTile((kb + 1) & 1, (kb + 1) * 32);
            asm volatile("cp.async.wait_group 1;");
        } else {
            asm volatile("cp.async.wait_group 0;");
        }
        __syncthreads();

        const unsigned (*Asc)[32] = As[cur];
        const unsigned (*Bsc)[64] = Bs[cur];
#pragma unroll
        for (int kt = 0; kt < 4; kt++) {
            const int c0 = (((2 * kt) ^ g) << 2) | t;
            const int c1 = (((2 * kt + 1) ^ g) << 2) | t;
            const int kr = kt * 8 + t;
            unsigned a[2][4];
            a[0][0] = Asc[rA0][c0];     a[0][1] = Asc[rA0 + 8][c0];
            a[0][2] = Asc[rA0][c1];     a[0][3] = Asc[rA0 + 8][c1];
            a[1][0] = Asc[rA1][c0];     a[1][1] = Asc[rA1 + 8][c0];
            a[1][2] = Asc[rA1][c1];     a[1][3] = Asc[rA1 + 8][c1];
            unsigned b[4][2];
#pragma unroll
            for (int nt = 0; nt < 4; nt++) {
                b[nt][0] = Bsc[kr][colB[nt]];
                b[nt][1] = Bsc[kr + 4][colB[nt]];
            }
#pragma unroll
            for (int mt = 0; mt < 2; mt++)
#pragma unroll
                for (int nt = 0; nt < 4; nt++)
                    MMA_TF32(acc[mt][nt][0], acc[mt][nt][1], acc[mt][nt][2], acc[mt][nt][3],
                             a[mt][0], a[mt][1], a[mt][2], a[mt][3],
                             b[nt][0], b[nt][1]);
        }
        __syncthreads();
    }

#pragma unroll
    for (int mt = 0; mt < 2; mt++) {
        int r0 = bm + wm + mt * 16 + g;
        int r1 = r0 + 8;
#pragma unroll
        for (int nt = 0; nt < 4; nt++) {
            int col = bn + wn + nt * 8 + 2 * t;
#pragma unroll
            for (int half = 0; half < 2; half++) {
                int row = half ? r1 : r0;
                if (row >= M) continue;
                float v0 = acc[mt][nt][half * 2 + 0];
                float v1 = acc[mt][nt][half * 2 + 1];
                if (bias) { v0 += bias[col]; v1 += bias[col + 1]; }
                if (MODE == 1) { v0 = v0 * sigf(v0); v1 = v1 * sigf(v1); }
                if (MODE == 0 || MODE == 1) { v0 = rnd_tf32(v0); v1 = rnd_tf32(v1); }
                if (MODE == 2) {
                    v0 = res[(size_t)row * ldc + col] + v0;
                    v1 = res[(size_t)row * ldc + col + 1] + v1;
                }
                if (MODE == 3) {
                    v0 = res[(size_t)row * ldc + col] + 0.5f * v0;
                    v1 = res[(size_t)row * ldc + col + 1] + 0.5f * v1;
                }
                *(float2*)&C[(size_t)row * ldc + col] = make_float2(v0, v1);
            }
        }
    }
}

// ---------------- LayerNorm: 128 threads, float4, warp shuffles ----------------
// RND: tf32-round outputs (when feeding a GEMM A-side)
template <bool RND>
__global__ void __launch_bounds__(128) ln_kernel(
    const float* __restrict__ x, const float* __restrict__ s,
    const float* __restrict__ b, float* __restrict__ out)
{
    __shared__ float red[8];
    const int row = blockIdx.x;
    const int tid = threadIdx.x;
    const int lane = tid & 31, wid = tid >> 5;
    float4 v = ((const float4*)(x + (size_t)row * Dd))[tid];

    float s1 = v.x + v.y + v.z + v.w;
#pragma unroll
    for (int o = 16; o > 0; o >>= 1) s1 += __shfl_xor_sync(0xffffffffu, s1, o);
    if (lane == 0) red[wid] = s1;
    __syncthreads();
    float mean = (red[0] + red[1] + red[2] + red[3]) * (1.0f / Dd);

    float4 d;
    d.x = v.x - mean; d.y = v.y - mean; d.z = v.z - mean; d.w = v.w - mean;
    float s2 = d.x * d.x + d.y * d.y + d.z * d.z + d.w * d.w;
#pragma unroll
    for (int o = 16; o > 0; o >>= 1) s2 += __shfl_xor_sync(0xffffffffu, s2, o);
    if (lane == 0) red[4 + wid] = s2;
    __syncthreads();
    float rstd = rsqrtf((red[4] + red[5] + red[6] + red[7]) * (1.0f / Dd) + EPSf);

    float4 sc = ((const float4*)s)[tid];
    float4 bc = ((const float4*)b)[tid];
    float4 o4;
    o4.x = d.x * rstd * sc.x + bc.x;
    o4.y = d.y * rstd * sc.y + bc.y;
    o4.z = d.z * rstd * sc.z + bc.z;
    o4.w = d.w * rstd * sc.w + bc.w;
    if (RND) {
        o4.x = rnd_tf32(o4.x); o4.y = rnd_tf32(o4.y);
        o4.z = rnd_tf32(o4.z); o4.w = rnd_tf32(o4.w);
    }
    ((float4*)(out + (size_t)row * Dd))[tid] = o4;
}

// =======================================================================
// rel-pos attention scores on tensor cores.
// S[b,h,t,s] = ((q+u)·k[s] + (q+v)·p[T-1-t+s]) * SCALE
// Decomposed: q·k (MMA) + q·p (MMA) + u·k[s] + v·p[pr] (rank-1 vecs).
// =======================================================================
__global__ void __launch_bounds__(256) attn_scores(
    const float* __restrict__ Q, const float* __restrict__ Km,
    const float* __restrict__ Pm,
    const float* __restrict__ bu, const float* __restrict__ bvv,
    float* __restrict__ S)
{
    __shared__ unsigned qs[32][66], kt[32][66], pw[64][66];
    __shared__ float C1[32][33];
    __shared__ float C2[32][68];
    __shared__ float uk[32], vp[64];
    __shared__ float us[64], vs[64];

    const int z = blockIdx.z;
    const int b = z >> 3, h = z & 7;
    const int t0 = blockIdx.y << 5, s0 = blockIdx.x << 5;
    const int tid = threadIdx.x;

    if (tid < 16)
        ((float4*)us)[tid] = ((const float4*)(bu + h * 64))[tid];
    else if (tid < 32)
        ((float4*)vs)[tid - 16] = ((const float4*)(bvv + h * 64))[tid - 16];

    for (int i = tid; i < 512; i += 256) {
        int r = i >> 4, c = (i & 15) * 4;
        float4 q4 = *(const float4*)&Q[(size_t)(b * Tn + t0 + r) * Dd + h * 64 + c];
        qs[r][c + 0] = f2tf32(q4.x);
        qs[r][c + 1] = f2tf32(q4.y);
        qs[r][c + 2] = f2tf32(q4.z);
        qs[r][c + 3] = f2tf32(q4.w);
        float4 k4 = *(const float4*)&Km[(size_t)(b * Tn + s0 + r) * Dd + h * 64 + c];
        kt[r][c + 0] = f2tf32(k4.x);
        kt[r][c + 1] = f2tf32(k4.y);
        kt[r][c + 2] = f2tf32(k4.z);
        kt[r][c + 3] = f2tf32(k4.w);
    }
    const int base = (Tn - 32) - t0 + s0;     // in [0, P-63]
    for (int i = tid; i < 1024; i += 256) {
        int r = i >> 4, c = (i & 15) * 4;
        if (r < 63) {
            float4 p4 = *(const float4*)&Pm[(size_t)(base + r) * Dd + h * 64 + c];
            pw[r][c + 0] = f2tf32(p4.x);
            pw[r][c + 1] = f2tf32(p4.y);
            pw[r][c + 2] = f2tf32(p4.z);
            pw[r][c + 3] = f2tf32(p4.w);
        } else {
            pw[r][c + 0] = 0u; pw[r][c + 1] = 0u; pw[r][c + 2] = 0u; pw[r][c + 3] = 0u;
        }
    }
    __syncthreads();

    const int warp = tid >> 5, lane = tid & 31;
    const int g = lane >> 2, t = lane & 3;
    const int mw  = (warp >> 2) * 16;
    const int nwA = (warp & 3) * 8;
    const int nw2 = (warp & 3) * 16;

    float c1r[4] = {};
    float e[2][4] = {};
#pragma unroll
    for (int k0 = 0; k0 < 64; k0 += 8) {
        const int k = k0 + t;
        unsigned a0 = qs[mw + g][k],     a1 = qs[mw + 8 + g][k];
        unsigned a2 = qs[mw + g][k + 4], a3 = qs[mw + 8 + g][k + 4];
        unsigned b0 = kt[nwA + g][k],    b1 = kt[nwA + g][k + 4];
        MMA_TF32(c1r[0], c1r[1], c1r[2], c1r[3], a0, a1, a2, a3, b0, b1);
#pragma unroll
        for (int nt = 0; nt < 2; nt++) {
            int nb = nw2 + nt * 8 + g;
            unsigned p0 = pw[nb][k], p1 = pw[nb][k + 4];
            MMA_TF32(e[nt][0], e[nt][1], e[nt][2], e[nt][3], a0, a1, a2, a3, p0, p1);
        }
    }
    C1[mw + g][nwA + 2 * t]         = c1r[0];
    C1[mw + g][nwA + 2 * t + 1]     = c1r[1];
    C1[mw + 8 + g][nwA + 2 * t]     = c1r[2];
    C1[mw + 8 + g][nwA + 2 * t + 1] = c1r[3];
#pragma unroll
    for (int nt = 0; nt < 2; nt++) {
        int nb = nw2 + nt * 8;
        C2[mw + g][nb + 2 * t]         = e[nt][0];
        C2[mw + g][nb + 2 * t + 1]     = e[nt][1];
        C2[mw + 8 + g][nb + 2 * t]     = e[nt][2];
        C2[mw + 8 + g][nb + 2 * t + 1] = e[nt][3];
    }

    if (tid < 32) {
        float s = 0.f;
#pragma unroll 8
        for (int d = 0; d < 64; d++) s += us[d] * __uint_as_float(kt[tid][d]);
        uk[tid] = s;
    } else if (tid < 96) {
        int r = tid - 32;
        float s = 0.f;
#pragma unroll 8
        for (int d = 0; d < 64; d++) s += vs[d] * __uint_as_float(pw[r][d]);
        vp[r] = s;
    }
    __syncthreads();

    const int tl = tid >> 3, sl = (tid & 7) * 4;
    const int pr = 31 - tl + sl;
    float4 o4;
    o4.x = (C1[tl][sl + 0] + uk[sl + 0] + C2[tl][pr + 0] + vp[pr + 0]) * SCALEf;
    o4.y = (C1[tl][sl + 1] + uk[sl + 1] + C2[tl][pr + 1] + vp[pr + 1]) * SCALEf;
    o4.z = (C1[tl][sl + 2] + uk[sl + 2] + C2[tl][pr + 2] + vp[pr + 2]) * SCALEf;
    o4.w = (C1[tl][sl + 3] + uk[sl + 3] + C2[tl][pr + 3] + vp[pr + 3]) * SCALEf;
    *(float4*)&S[((size_t)z * Tn + (t0 + tl)) * Tn + (s0 + sl)] = o4;
}

// ---------------- row softmax over T=1024 (tf32-rounded output) ----------------
__global__ void __launch_bounds__(256) softmax_kernel(float* __restrict__ S)
{
    __shared__ float red[256];
    float4* p = (float4*)(S + (size_t)blockIdx.x * Tn);
    const int tid = threadIdx.x;
    float4 x = p[tid];
    float m = fmaxf(fmaxf(x.x, x.y), fmaxf(x.z, x.w));
    red[tid] = m;
    __syncthreads();
    for (int o = 128; o > 0; o >>= 1) {
        if (tid < o) red[tid] = fmaxf(red[tid], red[tid + o]);
        __syncthreads();
    }
    m = red[0];
    __syncthreads();
    x.x = expf(x.x - m); x.y = expf(x.y - m); x.z = expf(x.z - m); x.w = expf(x.w - m);
    red[tid] = x.x + x.y + x.z + x.w;
    __syncthreads();
    for (int o = 128; o > 0; o >>= 1) {
        if (tid < o) red[tid] += red[tid + o];
        __syncthreads();
    }
    float inv = 1.0f / red[0];
    x.x = rnd_tf32(x.x * inv); x.y = rnd_tf32(x.y * inv);
    x.z = rnd_tf32(x.z * inv); x.w = rnd_tf32(x.w * inv);
    p[tid] = x;
}

// ---------------- GLU + transpose (B,T,2D) -> (B,D,T), tiled ----------------
__global__ void __launch_bounds__(256) glu_tr(const float* __restrict__ Y2,
                                              float* __restrict__ CV)
{
    __shared__ float tile[32][33];
    const int b = blockIdx.z;
    const int d0 = blockIdx.y * 32, t0 = blockIdx.x * 32;
    const int tid = threadIdx.x;
    const int rr = tid >> 5, cc = tid & 31;
#pragma unroll
    for (int i = 0; i < 4; i++) {
        int tl = rr + i * 8;
        size_t base = (size_t)(b * Tn + t0 + tl) * (2 * Dd) + d0 + cc;
        float a = Y2[base];
        float g = Y2[base + Dd];
        tile[tl][cc] = a * sigf(g);
    }
    __syncthreads();
#pragma unroll
    for (int i = 0; i < 4; i++) {
        int dl = rr + i * 8;
        CV[((size_t)b * Dd + d0 + dl) * Tn + t0 + cc] = tile[cc][dl];
    }
}

// ---------------- depthwise conv K=31, pad 15 ----------------
__global__ void __launch_bounds__(128) dwconv_kernel(
    const float* __restrict__ CV, const float* __restrict__ w,
    const float* __restrict__ bias, float* __restrict__ out)
{
    __shared__ float sin_[128 + 30];
    __shared__ float sw[31];
    const int t0 = blockIdx.x * 128;
    const int d = blockIdx.y;
    const int b = blockIdx.z;
    const float* ip = CV + ((size_t)b * Dd + d) * Tn;
    const int tid = threadIdx.x;
    for (int i = tid; i < 158; i += 128) {
        int t = t0 - 15 + i;
        sin_[i] = (t >= 0 && t < Tn) ? ip[t] : 0.0f;
    }
    if (tid < 31) sw[tid] = w[d * KWn + tid];
    __syncthreads();
    float acc = bias[d];
#pragma unroll
    for (int k = 0; k < 31; k++) acc += sin_[tid + k] * sw[k];
    out[((size_t)b * Dd + d) * Tn + t0 + tid] = acc;
}

// ---------------- BatchNorm stats ----------------
__global__ void __launch_bounds__(256) bn_stats(const float* __restrict__ y)
{
    __shared__ float rs[256], rs2[256];
    const int d = blockIdx.x;
    const int tid = threadIdx.x;
    float s = 0.f, s2 = 0.f;
    for (int b = 0; b < Bn; b++) {
        const float* p = y + ((size_t)b * Dd + d) * Tn;
        for (int t = tid; t < Tn; t += 256) {
            float v = p[t];
            s += v;
            s2 += v * v;
        }
    }
    rs[tid] = s; rs2[tid] = s2;
    __syncthreads();
    for (int o = 128; o > 0; o >>= 1) {
        if (tid < o) { rs[tid] += rs[tid + o]; rs2[tid] += rs2[tid + o]; }
        __syncthreads();
    }
    if (tid == 0) {
        float mu = rs[0] * (1.0f / (Bn * Tn));
        float var = rs2[0] * (1.0f / (Bn * Tn)) - mu * mu;
        g_mu[d] = mu;
        g_rstd[d] = rsqrtf(var + EPSf);
    }
}

// ---------------- BN apply + SiLU + transpose -> (B,T,D), tf32-rounded ----------------
__global__ void __launch_bounds__(256) bn_tr(
    const float* __restrict__ y, const float* __restrict__ g,
    const float* __restrict__ bt, float* __restrict__ out)
{
    __shared__ float tile[32][33];
    const int b = blockIdx.z;
    const int d0 = blockIdx.y * 32, t0 = blockIdx.x * 32;
    const int tid = threadIdx.x;
    const int rr = tid >> 5, cc = tid & 31;
#pragma unroll
    for (int i = 0; i < 4; i++) {
        int dl = rr + i * 8;
        int d = d0 + dl;
        float v = y[((size_t)b * Dd + d) * Tn + t0 + cc];
        v = (v - g_mu[d]) * g_rstd[d] * g[d] + bt[d];
        v = v * sigf(v);
        tile[dl][cc] = rnd_tf32(v);
    }
    __syncthreads();
#pragma unroll
    for (int i = 0; i < 4; i++) {
        int tl = rr + i * 8;
        out[(size_t)(b * Tn + t0 + tl) * Dd + d0 + cc] = tile[cc][tl];
    }
}

// ---------------- copies ----------------
__global__ void __launch_bounds__(256) copy_kernel(const float* __restrict__ in,
                                                   float* __restrict__ out, int n)
{
    int i = blockIdx.x * 256 + threadIdx.x;
    if (i < n) out[i] = in[i];
}
__global__ void __launch_bounds__(256) round_copy(const float* __restrict__ in,
                                                  float* __restrict__ out, int n)
{
    int i = blockIdx.x * 256 + threadIdx.x;
    if (i < n) out[i] = rnd_tf32(in[i]);
}

// ---------------- host-side launch helper ----------------
static void launch_tf32(int mode,
                        const float* A, int lda,
                        const float* W, int ldw,
                        const float* bias, const float* res,
                        float* C, int ldc,
                        int M, int N, int Kd)
{
    dim3 g(N / 64, (M + 127) / 128, 1);
    switch (mode) {
        case 0: tf32gemm<0, false><<<g, 256>>>(A, lda, W, ldw, bias, res, C, ldc, M, N, Kd); break;
        case 1: tf32gemm<1, false><<<g, 256>>>(A, lda, W, ldw, bias, res, C, ldc, M, N, Kd); break;
        case 2: tf32gemm<2, false><<<g, 256>>>(A, lda, W, ldw, bias, res, C, ldc, M, N, Kd); break;
        case 3: tf32gemm<3, false><<<g, 256>>>(A, lda, W, ldw, bias, res, C, ldc, M, N, Kd); break;
    }
}
static void rcopy(const float* src, float* dst, size_t n) {
    round_copy<<<(unsigned)((n + 255) / 256), 256>>>(src, dst, (int)n);
}

extern "C" void kernel_launch(void* const* d_in, const int* in_sizes, int n_in,
                              void* d_out, int out_size)
{
    const float* in_x   = (const float*)d_in[0];
    const float* pos    = (const float*)d_in[1];
    const float* ln_s   = (const float*)d_in[2];
    const float* ln_b   = (const float*)d_in[3];
    const float* ff1_w1 = (const float*)d_in[4];
    const float* ff1_b1 = (const float*)d_in[5];
    const float* ff1_w2 = (const float*)d_in[6];
    const float* ff1_b2 = (const float*)d_in[7];
    const float* ff2_w1 = (const float*)d_in[8];
    const float* ff2_b1 = (const float*)d_in[9];
    const float* ff2_w2 = (const float*)d_in[10];
    const float* ff2_b2 = (const float*)d_in[11];
    const float* wq     = (const float*)d_in[12];
    const float* bq     = (const float*)d_in[13];
    const float* wk     = (const float*)d_in[14];
    const float* bk     = (const float*)d_in[15];
    const float* wv     = (const float*)d_in[16];
    const float* bv     = (const float*)d_in[17];
    const float* wp     = (const float*)d_in[18];
    const float* wo     = (const float*)d_in[19];
    const float* bo     = (const float*)d_in[20];
    const float* bias_u = (const float*)d_in[21];
    const float* bias_v = (const float*)d_in[22];
    const float* pw1_w  = (const float*)d_in[23];
    const float* pw1_b  = (const float*)d_in[24];
    const float* dw_w   = (const float*)d_in[25];
    const float* dw_b   = (const float*)d_in[26];
    const float* bn_g   = (const float*)d_in[27];
    const float* bn_b   = (const float*)d_in[28];
    const float* pw2_w  = (const float*)d_in[29];
    const float* pw2_b  = (const float*)d_in[30];
    (void)in_sizes; (void)n_in; (void)out_size;

    float *X, *Hb, *FF, *Qb, *Kb, *Vb, *Pb, *Sb, *CTX, *Y2, *CV, *CV2, *WR, *PosR;
    cudaGetSymbolAddress((void**)&X,    g_X);
    cudaGetSymbolAddress((void**)&Hb,   g_H);
    cudaGetSymbolAddress((void**)&FF,   g_FF);
    cudaGetSymbolAddress((void**)&Qb,   g_Q);
    cudaGetSymbolAddress((void**)&Kb,   g_K);
    cudaGetSymbolAddress((void**)&Vb,   g_V);
    cudaGetSymbolAddress((void**)&Pb,   g_P);
    cudaGetSymbolAddress((void**)&Sb,   g_S);
    cudaGetSymbolAddress((void**)&CTX,  g_CTX);
    cudaGetSymbolAddress((void**)&Y2,   g_Y2);
    cudaGetSymbolAddress((void**)&CV,   g_CV);
    cudaGetSymbolAddress((void**)&CV2,  g_CV2);
    cudaGetSymbolAddress((void**)&WR,   g_WR);
    cudaGetSymbolAddress((void**)&PosR, g_PosR);

    // tf32-pre-round all GEMM B-operands (and pos, the one raw A-operand)
    rcopy(ff1_w1, WR + OFF_FF1W1, (size_t)Ln * Dd * DFFd);
    rcopy(ff1_w2, WR + OFF_FF1W2, (size_t)Ln * DFFd * Dd);
    rcopy(ff2_w1, WR + OFF_FF2W1, (size_t)Ln * Dd * DFFd);
    rcopy(ff2_w2, WR + OFF_FF2W2, (size_t)Ln * DFFd * Dd);
    rcopy(wq,     WR + OFF_WQ,    (size_t)Ln * Dd * Dd);
    rcopy(wk,     WR + OFF_WK,    (size_t)Ln * Dd * Dd);
    rcopy(wv,     WR + OFF_WV,    (size_t)Ln * Dd * Dd);
    rcopy(wo,     WR + OFF_WO,    (size_t)Ln * Dd * Dd);
    rcopy(wp,     WR + OFF_WP,    (size_t)Ln * Dd * Dd);
    rcopy(pw1_w,  WR + OFF_PW1,   (size_t)Ln * Dd * 2 * Dd);
    rcopy(pw2_w,  WR + OFF_PW2,   (size_t)Ln * Dd * Dd);
    rcopy(pos,    PosR,           (size_t)Pn * Dd);

    copy_kernel<<<(BTn * Dd) / 256, 256>>>(in_x, X, BTn * Dd);

    for (int l = 0; l < Ln; ++l) {
        const float* lnS = ln_s + (size_t)l * 5 * Dd;
        const float* lnB = ln_b + (size_t)l * 5 * Dd;

        // ---- macaron FFN 1 (half residual) ----
        ln_kernel<true><<<BTn, 128>>>(X, lnS, lnB, Hb);
        launch_tf32(1, Hb, Dd, WR + OFF_FF1W1 + (size_t)l * Dd * DFFd, DFFd,
                    ff1_b1 + (size_t)l * DFFd, nullptr, FF, DFFd, BTn, DFFd, Dd);
        launch_tf32(3, FF, DFFd, WR + OFF_FF1W2 + (size_t)l * DFFd * Dd, Dd,
                    ff1_b2 + (size_t)l * Dd, X, X, Dd, BTn, Dd, DFFd);

        // ---- rel-pos MHSA ----
        ln_kernel<true><<<BTn, 128>>>(X, lnS + Dd, lnB + Dd, Hb);
        launch_tf32(0, Hb, Dd, WR + OFF_WQ + (size_t)l * Dd * Dd, Dd,
                    bq + (size_t)l * Dd, nullptr, Qb, Dd, BTn, Dd, Dd);
        launch_tf32(0, Hb, Dd, WR + OFF_WK + (size_t)l * Dd * Dd, Dd,
                    bk + (size_t)l * Dd, nullptr, Kb, Dd, BTn, Dd, Dd);
        launch_tf32(0, Hb, Dd, WR + OFF_WV + (size_t)l * Dd * Dd, Dd,
                    bv + (size_t)l * Dd, nullptr, Vb, Dd, BTn, Dd, Dd);
        launch_tf32(0, PosR, Dd, WR + OFF_WP + (size_t)l * Dd * Dd, Dd,
                    nullptr, nullptr, Pb, Dd, Pn, Dd, Dd);

        attn_scores<<<dim3(Tn / 32, Tn / 32, Bn * Hn), 256>>>(
            Qb, Kb, Pb, bias_u + (size_t)l * Hn * DKn, bias_v + (size_t)l * Hn * DKn, Sb);
        softmax_kernel<<<Bn * Hn * Tn, 256>>>(Sb);

        tf32gemm<0, true><<<dim3(1, Tn / 128, Bn * Hn), 256>>>(
            Sb, Tn, Vb, Dd, nullptr, nullptr, CTX, Dd, Tn, DKn, Tn);

        launch_tf32(2, CTX, Dd, WR + OFF_WO + (size_t)l * Dd * Dd, Dd,
                    bo + (size_t)l * Dd, X, X, Dd, BTn, Dd, Dd);

        // ---- conv module ----
        ln_kernel<true><<<BTn, 128>>>(X, lnS + 2 * Dd, lnB + 2 * Dd, Hb);
        launch_tf32(0, Hb, Dd, WR + OFF_PW1 + (size_t)l * Dd * 2 * Dd, 2 * Dd,
                    pw1_b + (size_t)l * 2 * Dd, nullptr, Y2, 2 * Dd, BTn, 2 * Dd, Dd);
        glu_tr<<<dim3(Tn / 32, Dd / 32, Bn), 256>>>(Y2, CV);
        dwconv_kernel<<<dim3(Tn / 128, Dd, Bn), 128>>>(
            CV, dw_w + (size_t)l * Dd * KWn, dw_b + (size_t)l * Dd, CV2);
        bn_stats<<<Dd, 256>>>(CV2);
        bn_tr<<<dim3(Tn / 32, Dd / 32, Bn), 256>>>(
            CV2, bn_g + (size_t)l * Dd, bn_b + (size_t)l * Dd, Hb);
        launch_tf32(2, Hb, Dd, WR + OFF_PW2 + (size_t)l * Dd * Dd, Dd,
                    pw2_b + (size_t)l * Dd, X, X, Dd, BTn, Dd, Dd);

        // ---- macaron FFN 2 (half residual) ----
        ln_kernel<true><<<BTn, 128>>>(X, lnS + 3 * Dd, lnB + 3 * Dd, Hb);
        launch_tf32(1, Hb, Dd, WR + OFF_FF2W1 + (size_t)l * Dd * DFFd, DFFd,
                    ff2_b1 + (size_t)l * DFFd, nullptr, FF, DFFd, BTn, DFFd, Dd);
        launch_tf32(3, FF, DFFd, WR + OFF_FF2W2 + (size_t)l * DFFd * Dd, Dd,
                    ff2_b2 + (size_t)l * Dd, X, X, Dd, BTn, Dd, DFFd);

        // ---- final per-layer LN (full precision) ----
        float* outp = (l == Ln - 1) ? (float*)d_out : X;
        ln_kernel<false><<<BTn, 128>>>(X, lnS + 4 * Dd, lnB + 4 * Dd, outp);
    }
}